// round 3
// baseline (speedup 1.0000x reference)
#include <cuda_runtime.h>
#include <cuda_bf16.h>
#include <cstdint>

// Problem constants (match reference)
#define NN 100000      // nodes
#define DD 128         // feature dim
#define EE 200000      // edges per etype
#define ET 3           // etypes
#define NL 3           // layers
#define BN_EPS 1e-5f

// ---------------- device scratch (no allocs allowed) ----------------
__device__ float g_h[(size_t)NN * DD];      // features between layers
__device__ float g_pre[(size_t)NN * DD];    // pre-BN accumulated layer output
__device__ float g_neigh[(size_t)NN * DD];  // per-etype scatter-mean workspace
__device__ int   g_cnt[ET * NN];            // in-degree per etype
__device__ float g_inv[ET * NN];            // 1/max(cnt,1)
__device__ float g_stats[2 * DD];           // BN column sum / sumsq

// ---------------- utility: zero a float4 region ----------------
__global__ void zero_f4(float4* __restrict__ p, int n4) {
    int i = blockIdx.x * blockDim.x + threadIdx.x;
    int stride = gridDim.x * blockDim.x;
    float4 z = make_float4(0.f, 0.f, 0.f, 0.f);
    for (; i < n4; i += stride) p[i] = z;
}

// ---------------- degree count + inverse ----------------
__global__ void count_deg(const int* __restrict__ dst, int* __restrict__ cnt, int total, int E) {
    int i = blockIdx.x * blockDim.x + threadIdx.x;
    if (i >= total) return;
    int e = i / E;
    atomicAdd(&cnt[e * NN + dst[i]], 1);
}

__global__ void make_inv(const int* __restrict__ cnt, float* __restrict__ inv, int total) {
    int i = blockIdx.x * blockDim.x + threadIdx.x;
    if (i >= total) return;
    inv[i] = 1.0f / fmaxf((float)cnt[i], 1.0f);
}

// ---------------- scatter-add: one warp per edge, red.global.add.v4.f32 ----------------
__global__ void scatter_edges(const float* __restrict__ h,
                              const int* __restrict__ src,
                              const int* __restrict__ dst,
                              float* __restrict__ neigh, int nEdges) {
    int gwarp = (blockIdx.x * blockDim.x + threadIdx.x) >> 5;
    int lane  = threadIdx.x & 31;
    if (gwarp >= nEdges) return;
    int s = src[gwarp];
    int d = dst[gwarp];
    float4 v = *(const float4*)(h + (size_t)s * DD + lane * 4);
    float* p = neigh + (size_t)d * DD + lane * 4;
    asm volatile("red.global.add.v4.f32 [%0], {%1, %2, %3, %4};"
                 :: "l"(p), "f"(v.x), "f"(v.y), "f"(v.z), "f"(v.w)
                 : "memory");
}

// ---------------- fused GEMM: C (+)= relu( h@Ws + (neigh*inv)@Wn + bias ) ----------------
// Tiles: BM=64, BN=128 (full width), BK=32, K total = 256 (seg0: h/Ws, seg1: neigh/Wn)
#define GBM 64
#define GBN 128
#define GBK 32
__global__ __launch_bounds__(256)
void gemm_fused(const float* __restrict__ A0, const float* __restrict__ A1,
                const float* __restrict__ invc,
                const float* __restrict__ B0, const float* __restrict__ B1,
                const float* __restrict__ bias, float* __restrict__ C,
                int N, int doRelu, int accum) {
    __shared__ float As[GBM * GBK];   // [row][k]
    __shared__ float Bs[GBK * GBN];   // [k][n]

    int tid = threadIdx.x;
    int tx  = tid & 31;   // col group (4 cols)
    int ty  = tid >> 5;   // row group (8 rows)
    int blockRow = blockIdx.x * GBM;

    float4 acc[8];
#pragma unroll
    for (int i = 0; i < 8; ++i) acc[i] = make_float4(0.f, 0.f, 0.f, 0.f);

#pragma unroll 1
    for (int kt = 0; kt < 8; ++kt) {
        int kbase = kt * GBK;
        bool seg1 = (kbase >= DD);
        const float* A = seg1 ? A1 : A0;
        const float* B = seg1 ? B1 : B0;
        int koff = kbase & (DD - 1);

        // A tile: 2 float4 per thread
#pragma unroll
        for (int p = 0; p < 2; ++p) {
            int idx = tid + p * 256;          // 0..511
            int row = idx >> 3;               // 0..63
            int cv  = (idx & 7) * 4;
            int rg  = blockRow + row;
            float4 v = make_float4(0.f, 0.f, 0.f, 0.f);
            if (rg < N) {
                v = *(const float4*)(A + (size_t)rg * DD + koff + cv);
                if (seg1) {
                    float s = invc[rg];
                    v.x *= s; v.y *= s; v.z *= s; v.w *= s;
                }
            }
            *(float4*)(As + row * GBK + cv) = v;
        }
        // B tile: 4 float4 per thread
#pragma unroll
        for (int p = 0; p < 4; ++p) {
            int idx = tid + p * 256;          // 0..1023
            int row = idx >> 5;               // 0..31
            int cv  = (idx & 31) * 4;
            float4 v = *(const float4*)(B + (size_t)(koff + row) * DD + cv);
            *(float4*)(Bs + row * GBN + cv) = v;
        }
        __syncthreads();

#pragma unroll
        for (int k = 0; k < GBK; ++k) {
            float4 b = *(const float4*)(Bs + k * GBN + tx * 4);
#pragma unroll
            for (int i = 0; i < 8; ++i) {
                float a = As[(ty * 8 + i) * GBK + k];
                acc[i].x += a * b.x;
                acc[i].y += a * b.y;
                acc[i].z += a * b.z;
                acc[i].w += a * b.w;
            }
        }
        __syncthreads();
    }

    float4 bb = *(const float4*)(bias + tx * 4);
#pragma unroll
    for (int i = 0; i < 8; ++i) {
        int rg = blockRow + ty * 8 + i;
        if (rg >= N) break;
        float4 v;
        v.x = acc[i].x + bb.x;
        v.y = acc[i].y + bb.y;
        v.z = acc[i].z + bb.z;
        v.w = acc[i].w + bb.w;
        if (doRelu) {
            v.x = fmaxf(v.x, 0.f); v.y = fmaxf(v.y, 0.f);
            v.z = fmaxf(v.z, 0.f); v.w = fmaxf(v.w, 0.f);
        }
        float* cp = C + (size_t)rg * DD + tx * 4;
        if (accum) {
            float4 o = *(const float4*)cp;
            v.x += o.x; v.y += o.y; v.z += o.z; v.w += o.w;
        }
        *(float4*)cp = v;
    }
}

// ---------------- BatchNorm ----------------
__global__ void bn_stats(const float* __restrict__ x, float* __restrict__ stats, int N) {
    int col = threadIdx.x;   // 128 threads
    float s = 0.f, s2 = 0.f;
    for (int r = blockIdx.x; r < N; r += gridDim.x) {
        float v = x[(size_t)r * DD + col];
        s += v;
        s2 += v * v;
    }
    atomicAdd(&stats[col], s);
    atomicAdd(&stats[DD + col], s2);
}

__global__ void bn_apply(const float* __restrict__ x, const float* __restrict__ stats,
                         const float* __restrict__ gamma, const float* __restrict__ beta,
                         float* __restrict__ y, int N) {
    int col = threadIdx.x;
    float invN = 1.0f / (float)N;
    float mu  = stats[col] * invN;
    float var = stats[DD + col] * invN - mu * mu;
    float sc  = gamma[col] * rsqrtf(var + BN_EPS);
    float sh  = beta[col] - mu * sc;
    for (int r = blockIdx.x; r < N; r += gridDim.x) {
        size_t idx = (size_t)r * DD + col;
        y[idx] = x[idx] * sc + sh;
    }
}

// ---------------- launch ----------------
extern "C" void kernel_launch(void* const* d_in, const int* in_sizes, int n_in,
                              void* d_out, int out_size) {
    const float* feat  = (const float*)d_in[0];
    const int*   src   = (const int*)d_in[1];   // [ET, EE]
    const int*   dst   = (const int*)d_in[2];   // [ET, EE]
    const float* Wself = (const float*)d_in[3]; // [NL, ET, D, D]
    const float* Wngh  = (const float*)d_in[4];
    const float* bvec  = (const float*)d_in[5]; // [NL, ET, D]
    const float* gamma = (const float*)d_in[6]; // [NL, D]
    const float* beta  = (const float*)d_in[7];

    float *h, *pre, *neigh, *inv, *stats;
    int* cnt;
    cudaGetSymbolAddress((void**)&h,     g_h);
    cudaGetSymbolAddress((void**)&pre,   g_pre);
    cudaGetSymbolAddress((void**)&neigh, g_neigh);
    cudaGetSymbolAddress((void**)&cnt,   g_cnt);
    cudaGetSymbolAddress((void**)&inv,   g_inv);
    cudaGetSymbolAddress((void**)&stats, g_stats);

    const int n4_feat = NN * (DD / 4);       // 3.2M float4
    const int totE = ET * EE;
    const int totC = ET * NN;

    // degree counts (static per launch)
    zero_f4<<<1024, 256>>>((float4*)cnt, totC / 4);          // ET*NN ints = 300000 -> 75000 f4
    count_deg<<<(totE + 255) / 256, 256>>>(dst, cnt, totE, EE);
    make_inv<<<(totC + 255) / 256, 256>>>(cnt, inv, totC);

    const float* hin = feat;
    const int gemmGrid = (NN + GBM - 1) / GBM;               // 1563

    for (int l = 0; l < NL; ++l) {
        int doRelu = (l < NL - 1) ? 1 : 0;
        for (int e = 0; e < ET; ++e) {
            zero_f4<<<4096, 256>>>((float4*)neigh, n4_feat);
            scatter_edges<<<(EE * 32 + 255) / 256, 256>>>(hin, src + (size_t)e * EE,
                                                          dst + (size_t)e * EE, neigh, EE);
            const float* Ws = Wself + (size_t)(l * ET + e) * DD * DD;
            const float* Wn = Wngh  + (size_t)(l * ET + e) * DD * DD;
            const float* bb = bvec  + (size_t)(l * ET + e) * DD;
            gemm_fused<<<gemmGrid, 256>>>(hin, neigh, inv + (size_t)e * NN,
                                          Ws, Wn, bb, pre, NN, doRelu, (e > 0) ? 1 : 0);
        }
        zero_f4<<<1, 64>>>((float4*)stats, (2 * DD) / 4);
        bn_stats<<<512, DD>>>(pre, stats, NN);
        float* dest = (l == NL - 1) ? (float*)d_out : h;
        bn_apply<<<1024, DD>>>(pre, stats, gamma + (size_t)l * DD, beta + (size_t)l * DD,
                               dest, NN);
        hin = h;
    }
}

// round 4
// speedup vs baseline: 1.1661x; 1.1661x over previous
#include <cuda_runtime.h>
#include <cuda_bf16.h>
#include <cstdint>

// Problem constants (match reference)
#define NN 100000      // nodes
#define DD 128         // feature dim
#define EE 200000      // edges per etype
#define ET 3           // etypes
#define NL 3           // layers
#define BN_EPS 1e-5f

// ---------------- device scratch (no allocs allowed) ----------------
__device__ float g_h[(size_t)NN * DD];      // features between layers
__device__ float g_pre[(size_t)NN * DD];    // pre-BN accumulated layer output
__device__ float g_neigh[(size_t)NN * DD];  // per-etype scatter-mean workspace
__device__ int   g_cnt[ET * NN];            // in-degree per etype
__device__ float g_inv[ET * NN];            // 1/max(cnt,1)
__device__ float g_stats[2 * DD];           // BN column sum / sumsq

// ---------------- utility: zero a float4 region ----------------
__global__ void zero_f4(float4* __restrict__ p, int n4) {
    int i = blockIdx.x * blockDim.x + threadIdx.x;
    int stride = gridDim.x * blockDim.x;
    float4 z = make_float4(0.f, 0.f, 0.f, 0.f);
    for (; i < n4; i += stride) p[i] = z;
}

// ---------------- degree count + inverse ----------------
__global__ void count_deg(const int* __restrict__ dst, int* __restrict__ cnt, int total, int E) {
    int i = blockIdx.x * blockDim.x + threadIdx.x;
    if (i >= total) return;
    int e = i / E;
    atomicAdd(&cnt[e * NN + dst[i]], 1);
}

__global__ void make_inv(const int* __restrict__ cnt, float* __restrict__ inv, int total) {
    int i = blockIdx.x * blockDim.x + threadIdx.x;
    if (i >= total) return;
    inv[i] = 1.0f / fmaxf((float)cnt[i], 1.0f);
}

// ---------------- scatter-add: one warp per edge, red.global.add.v4.f32 ----------------
__global__ void scatter_edges(const float* __restrict__ h,
                              const int* __restrict__ src,
                              const int* __restrict__ dst,
                              float* __restrict__ neigh, int nEdges) {
    int gwarp = (blockIdx.x * blockDim.x + threadIdx.x) >> 5;
    int lane  = threadIdx.x & 31;
    if (gwarp >= nEdges) return;
    int s = src[gwarp];
    int d = dst[gwarp];
    float4 v = *(const float4*)(h + (size_t)s * DD + lane * 4);
    float* p = neigh + (size_t)d * DD + lane * 4;
    asm volatile("red.global.add.v4.f32 [%0], {%1, %2, %3, %4};"
                 :: "l"(p), "f"(v.x), "f"(v.y), "f"(v.z), "f"(v.w)
                 : "memory");
}

// ---------------- packed fp32x2 helpers (Blackwell FFMA2 path) ----------------
#define FFMA2(acc, a, b) \
    asm("fma.rn.f32x2 %0, %1, %2, %3;" : "=l"(acc) : "l"(a), "l"(b), "l"(acc))
#define PACK_DUP(out, f) \
    asm("mov.b64 %0, {%1, %1};" : "=l"(out) : "r"(__float_as_uint(f)))

// ---------------- fused GEMM: C (+)= relu( h@Ws + (neigh*inv)@Wn + bias ) ----------------
// Tiles: BM=64, BN=128 (full width), BK=32, K total = 256 (seg0: h/Ws, seg1: neigh/Wn)
// A tile stored k-major (stride 66) so row-pairs load as one LDS.64 -> f32x2 FMA.
#define GBM 64
#define GBN 128
#define GBK 32
#define ASTR 66   // padded row stride for k-major A tile (even for 8B align, breaks bank dup)
__global__ __launch_bounds__(256)
void gemm_fused(const float* __restrict__ A0, const float* __restrict__ A1,
                const float* __restrict__ invc,
                const float* __restrict__ B0, const float* __restrict__ B1,
                const float* __restrict__ bias, float* __restrict__ C,
                int N, int doRelu, int accum) {
    __shared__ __align__(16) float Ast[GBK * ASTR];  // [k][row]
    __shared__ __align__(16) float Bs[GBK * GBN];    // [k][n]

    int tid = threadIdx.x;
    int tx  = tid & 31;   // col group (4 cols)
    int ty  = tid >> 5;   // row group (8 rows)
    int blockRow = blockIdx.x * GBM;
    int rowbase  = ty * 8;

    // acc2[rp][j]: row pair (rowbase+2rp, rowbase+2rp+1), col tx*4+j, packed f32x2
    uint64_t acc2[4][4];
#pragma unroll
    for (int i = 0; i < 4; ++i)
#pragma unroll
        for (int j = 0; j < 4; ++j) acc2[i][j] = 0ull;

#pragma unroll 1
    for (int kt = 0; kt < 8; ++kt) {
        int kbase = kt * GBK;
        bool seg1 = (kbase >= DD);
        const float* A = seg1 ? A1 : A0;
        const float* B = seg1 ? B1 : B0;
        int koff = kbase & (DD - 1);

        // A tile: 2 float4 per thread, transposed into k-major smem
#pragma unroll
        for (int p = 0; p < 2; ++p) {
            int idx = tid + p * 256;          // 0..511
            int row = idx >> 3;               // 0..63
            int kq  = (idx & 7) * 4;          // 0..28
            int rg  = blockRow + row;
            float4 v = make_float4(0.f, 0.f, 0.f, 0.f);
            if (rg < N) {
                v = *(const float4*)(A + (size_t)rg * DD + koff + kq);
                if (seg1) {
                    float s = invc[rg];
                    v.x *= s; v.y *= s; v.z *= s; v.w *= s;
                }
            }
            Ast[(kq + 0) * ASTR + row] = v.x;
            Ast[(kq + 1) * ASTR + row] = v.y;
            Ast[(kq + 2) * ASTR + row] = v.z;
            Ast[(kq + 3) * ASTR + row] = v.w;
        }
        // B tile: 4 float4 per thread
#pragma unroll
        for (int p = 0; p < 4; ++p) {
            int idx = tid + p * 256;          // 0..1023
            int row = idx >> 5;               // 0..31
            int cv  = (idx & 31) * 4;
            float4 v = *(const float4*)(B + (size_t)(koff + row) * DD + cv);
            *(float4*)(Bs + row * GBN + cv) = v;
        }
        __syncthreads();

#pragma unroll
        for (int k = 0; k < GBK; ++k) {
            float4 b4 = *(const float4*)(Bs + k * GBN + tx * 4);
            uint64_t bb[4];
            PACK_DUP(bb[0], b4.x);
            PACK_DUP(bb[1], b4.y);
            PACK_DUP(bb[2], b4.z);
            PACK_DUP(bb[3], b4.w);
            const float* arow = Ast + k * ASTR + rowbase;
#pragma unroll
            for (int rp = 0; rp < 4; ++rp) {
                uint64_t ap = *(const uint64_t*)(arow + 2 * rp);  // broadcast LDS.64
                FFMA2(acc2[rp][0], ap, bb[0]);
                FFMA2(acc2[rp][1], ap, bb[1]);
                FFMA2(acc2[rp][2], ap, bb[2]);
                FFMA2(acc2[rp][3], ap, bb[3]);
            }
        }
        __syncthreads();
    }

    float4 bb4 = *(const float4*)(bias + tx * 4);
    float bias_a[4] = {bb4.x, bb4.y, bb4.z, bb4.w};
#pragma unroll
    for (int rp = 0; rp < 4; ++rp) {
#pragma unroll
        for (int half = 0; half < 2; ++half) {
            int rg = blockRow + rowbase + 2 * rp + half;
            if (rg >= N) continue;
            float v[4];
#pragma unroll
            for (int j = 0; j < 4; ++j) {
                uint64_t u = acc2[rp][j];
                uint32_t w = half ? (uint32_t)(u >> 32) : (uint32_t)u;
                v[j] = __uint_as_float(w) + bias_a[j];
                if (doRelu) v[j] = fmaxf(v[j], 0.f);
            }
            float* cp = C + (size_t)rg * DD + tx * 4;
            float4 out;
            if (accum) {
                float4 o = *(const float4*)cp;
                out = make_float4(v[0] + o.x, v[1] + o.y, v[2] + o.z, v[3] + o.w);
            } else {
                out = make_float4(v[0], v[1], v[2], v[3]);
            }
            *(float4*)cp = out;
        }
    }
}

// ---------------- BatchNorm ----------------
__global__ void bn_stats(const float* __restrict__ x, float* __restrict__ stats, int N) {
    int col = threadIdx.x;   // 128 threads
    float s = 0.f, s2 = 0.f;
    for (int r = blockIdx.x; r < N; r += gridDim.x) {
        float v = x[(size_t)r * DD + col];
        s += v;
        s2 += v * v;
    }
    atomicAdd(&stats[col], s);
    atomicAdd(&stats[DD + col], s2);
}

__global__ void bn_apply(const float* __restrict__ x, const float* __restrict__ stats,
                         const float* __restrict__ gamma, const float* __restrict__ beta,
                         float* __restrict__ y, int N) {
    int col = threadIdx.x;
    float invN = 1.0f / (float)N;
    float mu  = stats[col] * invN;
    float var = stats[DD + col] * invN - mu * mu;
    float sc  = gamma[col] * rsqrtf(var + BN_EPS);
    float sh  = beta[col] - mu * sc;
    for (int r = blockIdx.x; r < N; r += gridDim.x) {
        size_t idx = (size_t)r * DD + col;
        y[idx] = x[idx] * sc + sh;
    }
}

// ---------------- launch ----------------
extern "C" void kernel_launch(void* const* d_in, const int* in_sizes, int n_in,
                              void* d_out, int out_size) {
    const float* feat  = (const float*)d_in[0];
    const int*   src   = (const int*)d_in[1];   // [ET, EE]
    const int*   dst   = (const int*)d_in[2];   // [ET, EE]
    const float* Wself = (const float*)d_in[3]; // [NL, ET, D, D]
    const float* Wngh  = (const float*)d_in[4];
    const float* bvec  = (const float*)d_in[5]; // [NL, ET, D]
    const float* gamma = (const float*)d_in[6]; // [NL, D]
    const float* beta  = (const float*)d_in[7];

    float *h, *pre, *neigh, *inv, *stats;
    int* cnt;
    cudaGetSymbolAddress((void**)&h,     g_h);
    cudaGetSymbolAddress((void**)&pre,   g_pre);
    cudaGetSymbolAddress((void**)&neigh, g_neigh);
    cudaGetSymbolAddress((void**)&cnt,   g_cnt);
    cudaGetSymbolAddress((void**)&inv,   g_inv);
    cudaGetSymbolAddress((void**)&stats, g_stats);

    const int n4_feat = NN * (DD / 4);       // 3.2M float4
    const int totE = ET * EE;
    const int totC = ET * NN;

    // degree counts (static per launch)
    zero_f4<<<1024, 256>>>((float4*)cnt, totC / 4);
    count_deg<<<(totE + 255) / 256, 256>>>(dst, cnt, totE, EE);
    make_inv<<<(totC + 255) / 256, 256>>>(cnt, inv, totC);

    const float* hin = feat;
    const int gemmGrid = (NN + GBM - 1) / GBM;               // 1563

    for (int l = 0; l < NL; ++l) {
        int doRelu = (l < NL - 1) ? 1 : 0;
        for (int e = 0; e < ET; ++e) {
            zero_f4<<<4096, 256>>>((float4*)neigh, n4_feat);
            scatter_edges<<<(EE * 32 + 255) / 256, 256>>>(hin, src + (size_t)e * EE,
                                                          dst + (size_t)e * EE, neigh, EE);
            const float* Ws = Wself + (size_t)(l * ET + e) * DD * DD;
            const float* Wn = Wngh  + (size_t)(l * ET + e) * DD * DD;
            const float* bb = bvec  + (size_t)(l * ET + e) * DD;
            gemm_fused<<<gemmGrid, 256>>>(hin, neigh, inv + (size_t)e * NN,
                                          Ws, Wn, bb, pre, NN, doRelu, (e > 0) ? 1 : 0);
        }
        zero_f4<<<1, 64>>>((float4*)stats, (2 * DD) / 4);
        bn_stats<<<512, DD>>>(pre, stats, NN);
        float* dest = (l == NL - 1) ? (float*)d_out : h;
        bn_apply<<<1024, DD>>>(pre, stats, gamma + (size_t)l * DD, beta + (size_t)l * DD,
                               dest, NN);
        hin = h;
    }
}

// round 6
// speedup vs baseline: 1.3743x; 1.1785x over previous
#include <cuda_runtime.h>
#include <cuda_bf16.h>
#include <cstdint>

// Problem constants (match reference)
#define NN 100000      // nodes
#define DD 128         // feature dim
#define EE 200000      // edges per etype
#define ET 3           // etypes
#define NL 3           // layers
#define BN_EPS 1e-5f

#define NTILE 782      // ceil(NN/128)
#define GRID_MM 148

// ---------------- device scratch (no allocs allowed) ----------------
__device__ float g_h[(size_t)NN * DD];
__device__ float g_pre[(size_t)NN * DD];
__device__ float g_neigh[(size_t)ET * NN * DD];   // one buffer per etype
__device__ int   g_cnt[ET * NN];
__device__ float g_inv[ET * NN];
__device__ float g_stats[2 * DD];
__device__ __nv_bfloat16 g_wbf[(size_t)NL * ET * 2 * 2 * DD * DD]; // [l][e][mat][prec][n][k]

// ---------------- small kernels ----------------
__global__ void zero_f4(float4* __restrict__ p, int n4) {
    int i = blockIdx.x * blockDim.x + threadIdx.x;
    int stride = gridDim.x * blockDim.x;
    float4 z = make_float4(0.f, 0.f, 0.f, 0.f);
    for (; i < n4; i += stride) p[i] = z;
}

__global__ void count_deg(const int* __restrict__ dst, int* __restrict__ cnt, int total, int E) {
    int i = blockIdx.x * blockDim.x + threadIdx.x;
    if (i >= total) return;
    int e = i / E;
    atomicAdd(&cnt[e * NN + dst[i]], 1);
}

__global__ void make_inv(const int* __restrict__ cnt, float* __restrict__ inv, int total) {
    int i = blockIdx.x * blockDim.x + threadIdx.x;
    if (i >= total) return;
    inv[i] = 1.0f / fmaxf((float)cnt[i], 1.0f);
}

// scatter-add: one warp per edge, red.global.add.v4.f32
__global__ void scatter_edges(const float* __restrict__ h,
                              const int* __restrict__ src,
                              const int* __restrict__ dst,
                              float* __restrict__ neigh, int nEdges) {
    int gwarp = (blockIdx.x * blockDim.x + threadIdx.x) >> 5;
    int lane  = threadIdx.x & 31;
    if (gwarp >= nEdges) return;
    int s = src[gwarp];
    int d = dst[gwarp];
    float4 v = *(const float4*)(h + (size_t)s * DD + lane * 4);
    float* p = neigh + (size_t)d * DD + lane * 4;
    asm volatile("red.global.add.v4.f32 [%0], {%1, %2, %3, %4};"
                 :: "l"(p), "f"(v.x), "f"(v.y), "f"(v.z), "f"(v.w) : "memory");
}

// weights -> transposed bf16 hi/lo, once per launch
__global__ void prep_weights(const float* __restrict__ Ws, const float* __restrict__ Wn,
                             __nv_bfloat16* __restrict__ out) {
    int i = blockIdx.x * blockDim.x + threadIdx.x;
    const int total = NL * ET * 2 * DD * DD;
    if (i >= total) return;
    int k  = i & 127;
    int n  = (i >> 7) & 127;
    int m  = (i >> 14) & 1;
    int le = i >> 15;                 // 0..8 = l*ET+e
    const float* W = (m == 0 ? Ws : Wn) + (size_t)le * DD * DD;
    float x = W[k * DD + n];          // W[k][n] -> Bt[n][k] (col-major for mma row.col)
    __nv_bfloat16 h = __float2bfloat16(x);
    float r = x - __bfloat162float(h);
    size_t base = (size_t)((le * 2 + m) * 2) * DD * DD;
    out[base + n * DD + k]           = h;
    out[base + DD * DD + n * DD + k] = __float2bfloat16(r);
}

// ---------------- mma.sync GEMM machinery ----------------
__device__ __forceinline__ uint32_t smem_u32(const void* p) {
    uint32_t a;
    asm("{ .reg .u64 t; cvta.to.shared.u64 t, %1; cvt.u32.u64 %0, t; }" : "=r"(a) : "l"(p));
    return a;
}

#define LDSM4(rg, addr) \
    asm volatile("ldmatrix.sync.aligned.m8n8.x4.shared.b16 {%0,%1,%2,%3}, [%4];" \
                 : "=r"((rg)[0]), "=r"((rg)[1]), "=r"((rg)[2]), "=r"((rg)[3]) : "r"(addr))

#define MMA16816(d, a, b0, b1) \
    asm volatile("mma.sync.aligned.m16n8k16.row.col.f32.bf16.bf16.f32 " \
                 "{%0,%1,%2,%3}, {%4,%5,%6,%7}, {%8,%9}, {%0,%1,%2,%3};" \
                 : "+f"((d)[0]), "+f"((d)[1]), "+f"((d)[2]), "+f"((d)[3]) \
                 : "r"((a)[0]), "r"((a)[1]), "r"((a)[2]), "r"((a)[3]), "r"(b0), "r"(b1))

// swizzled smem chunk offset: row stride 256B, 16B chunks XOR'd with row&7
#define CHOFF(row, chunk) ((uint32_t)((row) * 256 + ((((chunk) ^ ((row) & 7))) << 4)))

// smem map (dynamic): [0,1536) bias; [2048,+64K) Ah; [+64K) An; [+64K) B
#define SM_AH 2048
#define SM_AN (SM_AH + 65536)
#define SM_B  (SM_AN + 65536)
#define SMEM_TOTAL (SM_B + 65536)
#define PREC_OFF 32768   // lo tile offset within each buffer

// fp32 tile -> bf16 hi/lo swizzled smem (optionally row-scaled)
__device__ __forceinline__ void convertA(const float* __restrict__ src,
                                         char* __restrict__ dst,
                                         const float* __restrict__ invp,
                                         int blockRow, int tid) {
#pragma unroll
    for (int p = 0; p < 8; ++p) {
        int g = tid + p * 256;            // 0..2047 chunk ids
        int row = g >> 4;
        int chunk = g & 15;
        int rg = blockRow + row;
        float x[8];
        if (rg < NN) {
            const float* s = src + (size_t)rg * DD + chunk * 8;
            float4 v0 = *(const float4*)s;
            float4 v1 = *(const float4*)(s + 4);
            x[0] = v0.x; x[1] = v0.y; x[2] = v0.z; x[3] = v0.w;
            x[4] = v1.x; x[5] = v1.y; x[6] = v1.z; x[7] = v1.w;
            if (invp) {
                float sc = invp[rg];
#pragma unroll
                for (int j = 0; j < 8; ++j) x[j] *= sc;
            }
        } else {
#pragma unroll
            for (int j = 0; j < 8; ++j) x[j] = 0.f;
        }
        uint32_t hi[4], lo[4];
#pragma unroll
        for (int j = 0; j < 4; ++j) {
            float a = x[2 * j], b = x[2 * j + 1];
            asm("cvt.rn.bf16x2.f32 %0, %1, %2;" : "=r"(hi[j]) : "f"(b), "f"(a));
            float ra = a - __uint_as_float(hi[j] << 16);
            float rb = b - __uint_as_float(hi[j] & 0xFFFF0000u);
            asm("cvt.rn.bf16x2.f32 %0, %1, %2;" : "=r"(lo[j]) : "f"(rb), "f"(ra));
        }
        uint32_t off = CHOFF(row, chunk);
        *(uint4*)(dst + off)            = make_uint4(hi[0], hi[1], hi[2], hi[3]);
        *(uint4*)(dst + PREC_OFF + off) = make_uint4(lo[0], lo[1], lo[2], lo[3]);
    }
}

// preconverted bf16 weights (hi+lo) -> swizzled smem
__device__ __forceinline__ void loadB(const __nv_bfloat16* __restrict__ Bsrc,
                                      char* __restrict__ dst, int tid) {
#pragma unroll
    for (int p = 0; p < 16; ++p) {
        int g = tid + p * 256;            // 0..4095
        int prec = g >> 11;
        int r = (g >> 4) & 127;
        int c = g & 15;
        uint4 v = *(const uint4*)(Bsrc + (size_t)prec * DD * DD + r * DD + c * 8);
        *(uint4*)(dst + prec * PREC_OFF + CHOFF(r, c)) = v;
    }
}

// one (A,B) pass: acc += Ahi@Bhi + Ahi@Blo + Alo@Bhi  (K=128)
__device__ __forceinline__ void compute_pass(uint32_t Asm, uint32_t Bsm,
                                             float acc[2][8][4], int lane, int wm, int wn) {
    int sub = lane >> 3, r = lane & 7;
    int arow0 = wm * 32 + r + (sub & 1) * 8;   // + mf*16
    int aco = sub >> 1;
    int brow0 = wn * 64 + r + (sub >> 1) * 8;  // + nb16*16
    int bco = sub & 1;
#pragma unroll
    for (int combo = 0; combo < 3; ++combo) {
        uint32_t Ao = Asm + (combo == 2 ? PREC_OFF : 0);
        uint32_t Bo = Bsm + (combo == 1 ? PREC_OFF : 0);
#pragma unroll
        for (int k16 = 0; k16 < 8; ++k16) {
            uint32_t a[2][4];
#pragma unroll
            for (int mf = 0; mf < 2; ++mf) {
                int row = arow0 + mf * 16;
                uint32_t addr = Ao + (uint32_t)(row * 256) +
                                ((((k16 * 2 + aco) ^ (row & 7))) << 4);
                LDSM4(a[mf], addr);
            }
            uint32_t b[4][4];
#pragma unroll
            for (int nb16 = 0; nb16 < 4; ++nb16) {
                int row = brow0 + nb16 * 16;
                uint32_t addr = Bo + (uint32_t)(row * 256) +
                                ((((k16 * 2 + bco) ^ (row & 7))) << 4);
                LDSM4(b[nb16], addr);
            }
#pragma unroll
            for (int mf = 0; mf < 2; ++mf)
#pragma unroll
                for (int nb16 = 0; nb16 < 4; ++nb16) {
                    MMA16816(acc[mf][2 * nb16],     a[mf], b[nb16][0], b[nb16][1]);
                    MMA16816(acc[mf][2 * nb16 + 1], a[mf], b[nb16][2], b[nb16][3]);
                }
        }
    }
}

// ---------------- persistent per-layer GEMM kernel ----------------
extern __shared__ __align__(1024) char dsm[];

__global__ void __launch_bounds__(256, 1)
mm_layer(const float* __restrict__ hin, const float* __restrict__ neigh,
         const float* __restrict__ inv, const __nv_bfloat16* __restrict__ wbf_l,
         const float* __restrict__ bias_l, float* __restrict__ pre, int doRelu) {
    int tid = threadIdx.x;
    int lane = tid & 31;
    int w = tid >> 5;
    int wm = w & 3, wn = w >> 2;

    for (int i = tid; i < ET * DD; i += 256)
        ((float*)dsm)[i] = bias_l[i];

    char* Ah = dsm + SM_AH;
    char* An = dsm + SM_AN;
    char* Bs = dsm + SM_B;
    uint32_t Ah_s = smem_u32(Ah);
    uint32_t An_s = smem_u32(An);
    uint32_t Bs_s = smem_u32(Bs);

    for (int tile = blockIdx.x; tile < NTILE; tile += gridDim.x) {
        int blockRow = tile * 128;
        convertA(hin, Ah, nullptr, blockRow, tid);

        float sum[2][8][4];
#pragma unroll
        for (int mf = 0; mf < 2; ++mf)
#pragma unroll
            for (int nb = 0; nb < 8; ++nb)
#pragma unroll
                for (int q = 0; q < 4; ++q) sum[mf][nb][q] = 0.f;

#pragma unroll 1
        for (int e = 0; e < ET; ++e) {
            convertA(neigh + (size_t)e * NN * DD, An, inv + e * NN, blockRow, tid);
            loadB(wbf_l + (size_t)((e * 2 + 0) * 2) * DD * DD, Bs, tid);
            __syncthreads();

            float acc[2][8][4];
#pragma unroll
            for (int mf = 0; mf < 2; ++mf)
#pragma unroll
                for (int nb = 0; nb < 8; ++nb)
#pragma unroll
                    for (int q = 0; q < 4; ++q) acc[mf][nb][q] = 0.f;

            compute_pass(Ah_s, Bs_s, acc, lane, wm, wn);
            __syncthreads();
            loadB(wbf_l + (size_t)((e * 2 + 1) * 2) * DD * DD, Bs, tid);
            __syncthreads();
            compute_pass(An_s, Bs_s, acc, lane, wm, wn);

            // bias + relu + fold into sum (register-only)
#pragma unroll
            for (int nb = 0; nb < 8; ++nb) {
                float2 bb = *(const float2*)((const float*)dsm + e * DD + wn * 64 +
                                             nb * 8 + (lane & 3) * 2);
#pragma unroll
                for (int mf = 0; mf < 2; ++mf) {
                    float v0 = acc[mf][nb][0] + bb.x;
                    float v1 = acc[mf][nb][1] + bb.y;
                    float v2 = acc[mf][nb][2] + bb.x;
                    float v3 = acc[mf][nb][3] + bb.y;
                    if (doRelu) {
                        v0 = fmaxf(v0, 0.f); v1 = fmaxf(v1, 0.f);
                        v2 = fmaxf(v2, 0.f); v3 = fmaxf(v3, 0.f);
                    }
                    sum[mf][nb][0] += v0; sum[mf][nb][1] += v1;
                    sum[mf][nb][2] += v2; sum[mf][nb][3] += v3;
                }
            }
            __syncthreads();   // An and Bs free for next etype
        }

        // write sum -> pre
#pragma unroll
        for (int mf = 0; mf < 2; ++mf) {
            int row0 = blockRow + wm * 32 + mf * 16 + (lane >> 2);
            int row1 = row0 + 8;
#pragma unroll
            for (int nb = 0; nb < 8; ++nb) {
                int col = wn * 64 + nb * 8 + (lane & 3) * 2;
                if (row0 < NN)
                    *(float2*)(pre + (size_t)row0 * DD + col) =
                        make_float2(sum[mf][nb][0], sum[mf][nb][1]);
                if (row1 < NN)
                    *(float2*)(pre + (size_t)row1 * DD + col) =
                        make_float2(sum[mf][nb][2], sum[mf][nb][3]);
            }
        }
        // no smem hazard: next convertA writes Ah, all reads of Ah done before
        // the last __syncthreads() of the e-loop
    }
}

// ---------------- BatchNorm ----------------
__global__ void bn_stats(const float* __restrict__ x, float* __restrict__ stats, int N) {
    int col = threadIdx.x;
    float s = 0.f, s2 = 0.f;
    for (int r = blockIdx.x; r < N; r += gridDim.x) {
        float v = x[(size_t)r * DD + col];
        s += v; s2 += v * v;
    }
    atomicAdd(&stats[col], s);
    atomicAdd(&stats[DD + col], s2);
}

__global__ void bn_apply(const float* __restrict__ x, const float* __restrict__ stats,
                         const float* __restrict__ gamma, const float* __restrict__ beta,
                         float* __restrict__ y, int N) {
    int col = threadIdx.x;
    float invN = 1.0f / (float)N;
    float mu  = stats[col] * invN;
    float var = stats[DD + col] * invN - mu * mu;
    float sc  = gamma[col] * rsqrtf(var + BN_EPS);
    float sh  = beta[col] - mu * sc;
    for (int r = blockIdx.x; r < N; r += gridDim.x) {
        size_t idx = (size_t)r * DD + col;
        y[idx] = x[idx] * sc + sh;
    }
}

// ---------------- launch ----------------
extern "C" void kernel_launch(void* const* d_in, const int* in_sizes, int n_in,
                              void* d_out, int out_size) {
    const float* feat  = (const float*)d_in[0];
    const int*   src   = (const int*)d_in[1];
    const int*   dst   = (const int*)d_in[2];
    const float* Wself = (const float*)d_in[3];
    const float* Wngh  = (const float*)d_in[4];
    const float* bvec  = (const float*)d_in[5];
    const float* gamma = (const float*)d_in[6];
    const float* beta  = (const float*)d_in[7];

    float *h, *pre, *neigh, *inv, *stats;
    int* cnt;
    __nv_bfloat16* wbf;
    cudaGetSymbolAddress((void**)&h,     g_h);
    cudaGetSymbolAddress((void**)&pre,   g_pre);
    cudaGetSymbolAddress((void**)&neigh, g_neigh);
    cudaGetSymbolAddress((void**)&cnt,   g_cnt);
    cudaGetSymbolAddress((void**)&inv,   g_inv);
    cudaGetSymbolAddress((void**)&stats, g_stats);
    cudaGetSymbolAddress((void**)&wbf,   g_wbf);

    cudaFuncSetAttribute(mm_layer, cudaFuncAttributeMaxDynamicSharedMemorySize, SMEM_TOTAL);

    const int n4_feat = NN * (DD / 4);
    const int totE = ET * EE;
    const int totC = ET * NN;

    zero_f4<<<1024, 256>>>((float4*)cnt, totC / 4);
    count_deg<<<(totE + 255) / 256, 256>>>(dst, cnt, totE, EE);
    make_inv<<<(totC + 255) / 256, 256>>>(cnt, inv, totC);
    prep_weights<<<(NL * ET * 2 * DD * DD + 255) / 256, 256>>>(Wself, Wngh, wbf);

    const float* hin = feat;

    for (int l = 0; l < NL; ++l) {
        int doRelu = (l < NL - 1) ? 1 : 0;
        for (int e = 0; e < ET; ++e) {
            float* ne = neigh + (size_t)e * NN * DD;
            zero_f4<<<4096, 256>>>((float4*)ne, n4_feat);
            scatter_edges<<<(EE * 32 + 255) / 256, 256>>>(hin, src + (size_t)e * EE,
                                                          dst + (size_t)e * EE, ne, EE);
        }
        mm_layer<<<GRID_MM, 256, SMEM_TOTAL>>>(hin, neigh, inv,
                                               wbf + (size_t)l * ET * 2 * 2 * DD * DD,
                                               bvec + (size_t)l * ET * DD,
                                               pre, doRelu);
        zero_f4<<<1, 64>>>((float4*)stats, (2 * DD) / 4);
        bn_stats<<<512, DD>>>(pre, stats, NN);
        float* dest = (l == NL - 1) ? (float*)d_out : h;
        bn_apply<<<1024, DD>>>(pre, stats, gamma + (size_t)l * DD, beta + (size_t)l * DD,
                               dest, NN);
        hin = h;
    }
}

// round 7
// speedup vs baseline: 1.5483x; 1.1266x over previous
#include <cuda_runtime.h>
#include <cuda_bf16.h>
#include <cstdint>

// Problem constants (match reference)
#define NN 100000      // nodes
#define DD 128         // feature dim
#define EE 200000      // edges per etype
#define ET 3           // etypes
#define NL 3           // layers
#define BN_EPS 1e-5f
#define PL (NN * DD)   // plane size (elements)

#define NTILE 782      // ceil(NN/128)
#define GRID_MM 148

// ---------------- device scratch (no allocs allowed) ----------------
__device__ float g_h[(size_t)PL];                      // fp32 h between layers
__device__ float g_pre[(size_t)PL];                    // pre-BN layer output
__device__ float g_neigh[(size_t)ET * PL];             // fp32 scatter workspace
__device__ int   g_cnt[ET * NN];
__device__ float g_inv[ET * NN];
__device__ float g_stats[2 * DD];
__device__ __nv_bfloat16 g_abf[(size_t)2 * PL];        // self A: [hi][lo] planes
__device__ __nv_bfloat16 g_nbf[(size_t)ET * 2 * PL];   // neigh A: per etype [hi][lo]
__device__ __nv_bfloat16 g_wbf[(size_t)NL * ET * 2 * 2 * DD * DD]; // [l][e][mat][prec][n][k]

// ---------------- helpers ----------------
__device__ __forceinline__ void split2(float a, float b, uint32_t& hi, uint32_t& lo) {
    asm("cvt.rn.bf16x2.f32 %0, %1, %2;" : "=r"(hi) : "f"(b), "f"(a));
    float ra = a - __uint_as_float(hi << 16);
    float rb = b - __uint_as_float(hi & 0xFFFF0000u);
    asm("cvt.rn.bf16x2.f32 %0, %1, %2;" : "=r"(lo) : "f"(rb), "f"(ra));
}
__device__ __forceinline__ uint32_t smem_u32(const void* p) {
    uint32_t a;
    asm("{ .reg .u64 t; cvta.to.shared.u64 t, %1; cvt.u32.u64 %0, t; }" : "=r"(a) : "l"(p));
    return a;
}
__device__ __forceinline__ void cpa16(uint32_t dst, const void* src, uint32_t srcsize) {
    asm volatile("cp.async.cg.shared.global [%0], [%1], 16, %2;"
                 :: "r"(dst), "l"(src), "r"(srcsize) : "memory");
}
#define CPA_COMMIT() asm volatile("cp.async.commit_group;" ::: "memory")
#define CPA_WAIT1()  asm volatile("cp.async.wait_group 1;" ::: "memory")

#define LDSM4(rg, addr) \
    asm volatile("ldmatrix.sync.aligned.m8n8.x4.shared.b16 {%0,%1,%2,%3}, [%4];" \
                 : "=r"((rg)[0]), "=r"((rg)[1]), "=r"((rg)[2]), "=r"((rg)[3]) : "r"(addr))
#define MMA16816(d, a, b0, b1) \
    asm volatile("mma.sync.aligned.m16n8k16.row.col.f32.bf16.bf16.f32 " \
                 "{%0,%1,%2,%3}, {%4,%5,%6,%7}, {%8,%9}, {%0,%1,%2,%3};" \
                 : "+f"((d)[0]), "+f"((d)[1]), "+f"((d)[2]), "+f"((d)[3]) \
                 : "r"((a)[0]), "r"((a)[1]), "r"((a)[2]), "r"((a)[3]), "r"(b0), "r"(b1))

// swizzled smem chunk offset: row stride 256B, 16B chunks XOR'd with row&7
#define CHOFF(row, chunk) ((uint32_t)((row) * 256 + ((((chunk) ^ ((row) & 7))) << 4)))

// ---------------- small kernels ----------------
__global__ void zero_f4(float4* __restrict__ p, int n4) {
    int i = blockIdx.x * blockDim.x + threadIdx.x;
    int stride = gridDim.x * blockDim.x;
    float4 z = make_float4(0.f, 0.f, 0.f, 0.f);
    for (; i < n4; i += stride) p[i] = z;
}

__global__ void count_deg(const int* __restrict__ dst, int* __restrict__ cnt, int total, int E) {
    int i = blockIdx.x * blockDim.x + threadIdx.x;
    if (i >= total) return;
    int e = i / E;
    atomicAdd(&cnt[e * NN + dst[i]], 1);
}

__global__ void make_inv(const int* __restrict__ cnt, float* __restrict__ inv, int total) {
    int i = blockIdx.x * blockDim.x + threadIdx.x;
    if (i >= total) return;
    inv[i] = 1.0f / fmaxf((float)cnt[i], 1.0f);
}

// scatter-add all etypes: one warp per edge
__global__ void scatter_all(const float* __restrict__ h,
                            const int* __restrict__ src,
                            const int* __restrict__ dst,
                            float* __restrict__ neigh, int totalEdges) {
    int gwarp = (blockIdx.x * blockDim.x + threadIdx.x) >> 5;
    int lane  = threadIdx.x & 31;
    if (gwarp >= totalEdges) return;
    int e = gwarp / EE;
    int s = src[gwarp];
    int d = dst[gwarp];
    float4 v = *(const float4*)(h + (size_t)s * DD + lane * 4);
    float* p = neigh + (size_t)e * PL + (size_t)d * DD + lane * 4;
    asm volatile("red.global.add.v4.f32 [%0], {%1, %2, %3, %4};"
                 :: "l"(p), "f"(v.x), "f"(v.y), "f"(v.z), "f"(v.w) : "memory");
}

// weights -> transposed bf16 hi/lo, once per launch
__global__ void prep_weights(const float* __restrict__ Ws, const float* __restrict__ Wn,
                             __nv_bfloat16* __restrict__ out) {
    int i = blockIdx.x * blockDim.x + threadIdx.x;
    const int total = NL * ET * 2 * DD * DD;
    if (i >= total) return;
    int k  = i & 127;
    int n  = (i >> 7) & 127;
    int m  = (i >> 14) & 1;
    int le = i >> 15;
    const float* W = (m == 0 ? Ws : Wn) + (size_t)le * DD * DD;
    float x = W[k * DD + n];          // W[k][n] -> Bt[n][k]
    __nv_bfloat16 h = __float2bfloat16(x);
    float r = x - __bfloat162float(h);
    size_t base = (size_t)((le * 2 + m) * 2) * DD * DD;
    out[base + n * DD + k]           = h;
    out[base + DD * DD + n * DD + k] = __float2bfloat16(r);
}

// fp32 plane -> bf16 hi/lo planes (feat / layer-0 A)
__global__ void cvt_plain(const float* __restrict__ src, __nv_bfloat16* __restrict__ dst, int n8) {
    int i = blockIdx.x * blockDim.x + threadIdx.x;
    if (i >= n8) return;
    const float4* s = (const float4*)src + (size_t)i * 2;
    float4 v0 = s[0], v1 = s[1];
    uint32_t hi[4], lo[4];
    split2(v0.x, v0.y, hi[0], lo[0]); split2(v0.z, v0.w, hi[1], lo[1]);
    split2(v1.x, v1.y, hi[2], lo[2]); split2(v1.z, v1.w, hi[3], lo[3]);
    *(uint4*)(dst + (size_t)i * 8)      = make_uint4(hi[0], hi[1], hi[2], hi[3]);
    *(uint4*)(dst + PL + (size_t)i * 8) = make_uint4(lo[0], lo[1], lo[2], lo[3]);
}

// neigh fp32 * inv -> bf16 hi/lo per etype
__global__ void finalize_neigh(const float* __restrict__ neigh, const float* __restrict__ inv,
                               __nv_bfloat16* __restrict__ nbf) {
    int i = blockIdx.x * blockDim.x + threadIdx.x;
    const int per = PL / 8;
    if (i >= ET * per) return;
    int e = i / per;
    int off = i - e * per;
    int row = off >> 4;                 // off*8/128
    float sc = inv[e * NN + row];
    const float4* s = (const float4*)(neigh + (size_t)e * PL) + (size_t)off * 2;
    float4 v0 = s[0], v1 = s[1];
    v0.x *= sc; v0.y *= sc; v0.z *= sc; v0.w *= sc;
    v1.x *= sc; v1.y *= sc; v1.z *= sc; v1.w *= sc;
    uint32_t hi[4], lo[4];
    split2(v0.x, v0.y, hi[0], lo[0]); split2(v0.z, v0.w, hi[1], lo[1]);
    split2(v1.x, v1.y, hi[2], lo[2]); split2(v1.z, v1.w, hi[3], lo[3]);
    __nv_bfloat16* d = nbf + (size_t)e * 2 * PL;
    *(uint4*)(d + (size_t)off * 8)      = make_uint4(hi[0], hi[1], hi[2], hi[3]);
    *(uint4*)(d + PL + (size_t)off * 8) = make_uint4(lo[0], lo[1], lo[2], lo[3]);
}

// ---------------- BatchNorm ----------------
__global__ void bn_stats(const float* __restrict__ x, float* __restrict__ stats, int N) {
    int col = threadIdx.x;
    float s = 0.f, s2 = 0.f;
    for (int r = blockIdx.x; r < N; r += gridDim.x) {
        float v = x[(size_t)r * DD + col];
        s += v; s2 += v * v;
    }
    atomicAdd(&stats[col], s);
    atomicAdd(&stats[DD + col], s2);
}

// BN apply -> fp32 y AND bf16 hi/lo planes (inner layers)
__global__ void bn_apply_fused(const float* __restrict__ x, const float* __restrict__ stats,
                               const float* __restrict__ gamma, const float* __restrict__ beta,
                               float* __restrict__ y, __nv_bfloat16* __restrict__ abf, int N) {
    int c2 = threadIdx.x;               // 64 threads -> col pair (2c2, 2c2+1)
    int c0 = 2 * c2, c1 = c0 + 1;
    float invN = 1.0f / (float)N;
    float mu0 = stats[c0] * invN, mu1 = stats[c1] * invN;
    float va0 = stats[DD + c0] * invN - mu0 * mu0;
    float va1 = stats[DD + c1] * invN - mu1 * mu1;
    float sc0 = gamma[c0] * rsqrtf(va0 + BN_EPS);
    float sc1 = gamma[c1] * rsqrtf(va1 + BN_EPS);
    float sh0 = beta[c0] - mu0 * sc0;
    float sh1 = beta[c1] - mu1 * sc1;
    uint32_t* hip = (uint32_t*)abf;
    uint32_t* lop = (uint32_t*)(abf + PL);
    for (int r = blockIdx.x; r < N; r += gridDim.x) {
        size_t idx = (size_t)r * DD + c0;
        float2 v = *(const float2*)(x + idx);
        float y0 = v.x * sc0 + sh0;
        float y1 = v.y * sc1 + sh1;
        *(float2*)(y + idx) = make_float2(y0, y1);
        uint32_t hi, lo;
        split2(y0, y1, hi, lo);
        hip[idx >> 1] = hi;
        lop[idx >> 1] = lo;
    }
}

__global__ void bn_apply(const float* __restrict__ x, const float* __restrict__ stats,
                         const float* __restrict__ gamma, const float* __restrict__ beta,
                         float* __restrict__ y, int N) {
    int col = threadIdx.x;
    float invN = 1.0f / (float)N;
    float mu  = stats[col] * invN;
    float var = stats[DD + col] * invN - mu * mu;
    float sc  = gamma[col] * rsqrtf(var + BN_EPS);
    float sh  = beta[col] - mu * sc;
    for (int r = blockIdx.x; r < N; r += gridDim.x) {
        size_t idx = (size_t)r * DD + col;
        y[idx] = x[idx] * sc + sh;
    }
}

// ---------------- persistent cp.async-pipelined bf16 GEMM ----------------
// smem: [0,2048) bias; A bufs 2x64KB; B piece bufs 3x32KB. Total 231424 B.
#define SM_BIAS 0
#define SM_A0   2048
#define SM_B0   (2048 + 2 * 65536)
#define SMEM_TOTAL (2048 + 2 * 65536 + 3 * 32768)

extern __shared__ __align__(1024) char dsm[];

// A stage: 4096 16B chunks (hi plane then lo plane), 512 threads
__device__ __forceinline__ void stageA(uint32_t dstbase, const __nv_bfloat16* __restrict__ g,
                                       int blockRow, int tid) {
#pragma unroll
    for (int p = 0; p < 8; ++p) {
        int c = tid + p * 512;
        int prec = c >> 11;
        int row  = (c >> 4) & 127;
        int ch   = c & 15;
        int rg = blockRow + row;
        int rs = rg < NN ? rg : 0;
        const void* src = g + (size_t)prec * PL + (size_t)rs * DD + ch * 8;
        cpa16(dstbase + prec * 32768 + CHOFF(row, ch), src, rg < NN ? 16u : 0u);
    }
}
// B stage: one 32KB piece (128 n-rows x 128 k)
__device__ __forceinline__ void stageB(uint32_t dstbase, const __nv_bfloat16* __restrict__ g,
                                       int tid) {
#pragma unroll
    for (int p = 0; p < 4; ++p) {
        int c = tid + p * 512;
        int row = c >> 4;
        int ch  = c & 15;
        cpa16(dstbase + CHOFF(row, ch), g + (size_t)row * DD + ch * 8, 16u);
    }
}

__device__ __forceinline__ void combo(uint32_t Abase, uint32_t Bbase,
                                      float acc[2][4][4], int lane, int wm, int wn) {
    int sub = lane >> 3, r = lane & 7;
    int arow0 = wm * 32 + r + (sub & 1) * 8;
    int aco = sub >> 1;
    int brow0 = wn * 32 + r + (sub >> 1) * 8;
    int bco = sub & 1;
#pragma unroll
    for (int k16 = 0; k16 < 8; ++k16) {
        uint32_t a[2][4];
#pragma unroll
        for (int mf = 0; mf < 2; ++mf) {
            int row = arow0 + mf * 16;
            LDSM4(a[mf], Abase + (uint32_t)(row * 256) + ((((k16 * 2 + aco) ^ (row & 7))) << 4));
        }
        uint32_t b[2][4];
#pragma unroll
        for (int n16 = 0; n16 < 2; ++n16) {
            int row = brow0 + n16 * 16;
            LDSM4(b[n16], Bbase + (uint32_t)(row * 256) + ((((k16 * 2 + bco) ^ (row & 7))) << 4));
        }
#pragma unroll
        for (int mf = 0; mf < 2; ++mf)
#pragma unroll
            for (int n16 = 0; n16 < 2; ++n16) {
                MMA16816(acc[mf][2 * n16],     a[mf], b[n16][0], b[n16][1]);
                MMA16816(acc[mf][2 * n16 + 1], a[mf], b[n16][2], b[n16][3]);
            }
    }
}

__global__ void __launch_bounds__(512, 1)
mm_layer(const __nv_bfloat16* __restrict__ abf, const __nv_bfloat16* __restrict__ nbf,
         const __nv_bfloat16* __restrict__ wbf_l, const float* __restrict__ bias_l,
         float* __restrict__ pre, int doRelu) {
    int tid = threadIdx.x;
    int lane = tid & 31;
    int w = tid >> 5;
    int wm = w & 3, wn = w >> 2;

    if (tid < ET * DD) ((float*)(dsm + SM_BIAS))[tid] = bias_l[tid];

    uint32_t sb = smem_u32(dsm);
    uint32_t Aaddr[2] = {sb + SM_A0, sb + SM_A0 + 65536};
    uint32_t Baddr[3] = {sb + SM_B0, sb + SM_B0 + 32768, sb + SM_B0 + 2 * 32768};

    // per-pass global sources (same for every tile except A blockRow)
    // pass p: even -> self (abf, Ws[e]); odd -> neigh (nbf[e], Wn[e]); e = p>>1
    const __nv_bfloat16* Asrc[6];
    const __nv_bfloat16* Bsrc[6];
#pragma unroll
    for (int p = 0; p < 6; ++p) {
        int e = p >> 1, mat = p & 1;
        Asrc[p] = mat ? (nbf + (size_t)e * 2 * PL) : abf;
        Bsrc[p] = wbf_l + (size_t)((e * 2 + mat) * 2) * DD * DD;  // hi at +0, lo at +DD*DD
    }

    int tile0 = blockIdx.x;
    // prologue for first tile: {A0,H0} commit, {L0} commit
    if (tile0 < NTILE) {
        stageA(Aaddr[0], Asrc[0], tile0 * 128, tid);
        stageB(Baddr[0], Bsrc[0], tid);
        CPA_COMMIT();
        stageB(Baddr[1], Bsrc[0] + DD * DD, tid);
        CPA_COMMIT();
    }

    for (int tile = tile0; tile < NTILE; tile += gridDim.x) {
        int blockRow = tile * 128;
        int nextRow = (tile + gridDim.x) * 128;
        bool hasNext = (tile + gridDim.x) < NTILE;

        float sum[2][4][4];
#pragma unroll
        for (int mf = 0; mf < 2; ++mf)
#pragma unroll
            for (int nb = 0; nb < 4; ++nb)
#pragma unroll
                for (int q = 0; q < 4; ++q) sum[mf][nb][q] = 0.f;

        float acc[2][4][4];

#pragma unroll 1
        for (int p = 0; p < 6; ++p) {
            __syncthreads();   // all warps done with buffers being re-staged below
            // entry stage: {A_{p+1}, H_{p+1}} (or next tile's {A0,H0})
            if (p < 5) {
                stageA(Aaddr[(p + 1) & 1], Asrc[p + 1], blockRow, tid);
                stageB(Baddr[(2 * p + 2) % 3], Bsrc[p + 1], tid);
            } else if (hasNext) {
                stageA(Aaddr[0], Asrc[0], nextRow, tid);
                stageB(Baddr[0], Bsrc[0], tid);
            }
            CPA_COMMIT();
            CPA_WAIT1();
            __syncthreads();

            uint32_t Acur = Aaddr[p & 1];
            uint32_t Hb = Baddr[(2 * p) % 3];
            uint32_t Lb = Baddr[(2 * p + 1) % 3];

            if (!(p & 1)) {
#pragma unroll
                for (int mf = 0; mf < 2; ++mf)
#pragma unroll
                    for (int nb = 0; nb < 4; ++nb)
#pragma unroll
                        for (int q = 0; q < 4; ++q) acc[mf][nb][q] = 0.f;
            }

            combo(Acur,         Hb, acc, lane, wm, wn);   // Ahi * Bhi
            combo(Acur + 32768, Hb, acc, lane, wm, wn);   // Alo * Bhi
            __syncthreads();    // Hb free for re-stage
            // mid stage: {L_{p+1}} (or next tile's {L0})
            if (p < 5) {
                stageB(Baddr[(2 * p + 3) % 3], Bsrc[p + 1] + DD * DD, tid);
            } else if (hasNext) {
                stageB(Baddr[1], Bsrc[0] + DD * DD, tid);
            }
            CPA_COMMIT();
            combo(Acur, Lb, acc, lane, wm, wn);           // Ahi * Blo

            if (p & 1) {
                int e = p >> 1;
#pragma unroll
                for (int nb = 0; nb < 4; ++nb) {
                    float2 bb = *(const float2*)((const float*)(dsm + SM_BIAS) + e * DD +
                                                 wn * 32 + nb * 8 + (lane & 3) * 2);
#pragma unroll
                    for (int mf = 0; mf < 2; ++mf) {
                        float v0 = acc[mf][nb][0] + bb.x;
                        float v1 = acc[mf][nb][1] + bb.y;
                        float v2 = acc[mf][nb][2] + bb.x;
                        float v3 = acc[mf][nb][3] + bb.y;
                        if (doRelu) {
                            v0 = fmaxf(v0, 0.f); v1 = fmaxf(v1, 0.f);
                            v2 = fmaxf(v2, 0.f); v3 = fmaxf(v3, 0.f);
                        }
                        sum[mf][nb][0] += v0; sum[mf][nb][1] += v1;
                        sum[mf][nb][2] += v2; sum[mf][nb][3] += v3;
                    }
                }
            }
        }

        // write sum -> pre
#pragma unroll
        for (int mf = 0; mf < 2; ++mf) {
            int row0 = blockRow + wm * 32 + mf * 16 + (lane >> 2);
            int row1 = row0 + 8;
#pragma unroll
            for (int nb = 0; nb < 4; ++nb) {
                int col = wn * 32 + nb * 8 + (lane & 3) * 2;
                if (row0 < NN)
                    *(float2*)(pre + (size_t)row0 * DD + col) =
                        make_float2(sum[mf][nb][0], sum[mf][nb][1]);
                if (row1 < NN)
                    *(float2*)(pre + (size_t)row1 * DD + col) =
                        make_float2(sum[mf][nb][2], sum[mf][nb][3]);
            }
        }
    }
}

// ---------------- launch ----------------
extern "C" void kernel_launch(void* const* d_in, const int* in_sizes, int n_in,
                              void* d_out, int out_size) {
    const float* feat  = (const float*)d_in[0];
    const int*   src   = (const int*)d_in[1];
    const int*   dst   = (const int*)d_in[2];
    const float* Wself = (const float*)d_in[3];
    const float* Wngh  = (const float*)d_in[4];
    const float* bvec  = (const float*)d_in[5];
    const float* gamma = (const float*)d_in[6];
    const float* beta  = (const float*)d_in[7];

    float *h, *pre, *neigh, *inv, *stats;
    int* cnt;
    __nv_bfloat16 *wbf, *abf, *nbf;
    cudaGetSymbolAddress((void**)&h,     g_h);
    cudaGetSymbolAddress((void**)&pre,   g_pre);
    cudaGetSymbolAddress((void**)&neigh, g_neigh);
    cudaGetSymbolAddress((void**)&cnt,   g_cnt);
    cudaGetSymbolAddress((void**)&inv,   g_inv);
    cudaGetSymbolAddress((void**)&stats, g_stats);
    cudaGetSymbolAddress((void**)&wbf,   g_wbf);
    cudaGetSymbolAddress((void**)&abf,   g_abf);
    cudaGetSymbolAddress((void**)&nbf,   g_nbf);

    cudaFuncSetAttribute(mm_layer, cudaFuncAttributeMaxDynamicSharedMemorySize, SMEM_TOTAL);

    const int totE = ET * EE;
    const int totC = ET * NN;

    zero_f4<<<1024, 256>>>((float4*)cnt, totC / 4);
    count_deg<<<(totE + 255) / 256, 256>>>(dst, cnt, totE, EE);
    make_inv<<<(totC + 255) / 256, 256>>>(cnt, inv, totC);
    prep_weights<<<(NL * ET * 2 * DD * DD + 255) / 256, 256>>>(Wself, Wngh, wbf);
    cvt_plain<<<(PL / 8 + 255) / 256, 256>>>(feat, abf, PL / 8);

    const float* hin = feat;

    for (int l = 0; l < NL; ++l) {
        int doRelu = (l < NL - 1) ? 1 : 0;
        zero_f4<<<8192, 256>>>((float4*)neigh, ET * PL / 4);
        scatter_all<<<(totE * 32 + 255) / 256, 256>>>(hin, src, dst, neigh, totE);
        finalize_neigh<<<(ET * PL / 8 + 255) / 256, 256>>>(neigh, inv, nbf);
        mm_layer<<<GRID_MM, 512, SMEM_TOTAL>>>(abf, nbf,
                                               wbf + (size_t)l * ET * 2 * 2 * DD * DD,
                                               bvec + (size_t)l * ET * DD, pre, doRelu);
        zero_f4<<<1, 64>>>((float4*)stats, (2 * DD) / 4);
        bn_stats<<<512, DD>>>(pre, stats, NN);
        if (l < NL - 1) {
            bn_apply_fused<<<2048, 64>>>(pre, stats, gamma + (size_t)l * DD,
                                         beta + (size_t)l * DD, h, abf, NN);
            hin = h;
        } else {
            bn_apply<<<1024, DD>>>(pre, stats, gamma + (size_t)l * DD,
                                   beta + (size_t)l * DD, (float*)d_out, NN);
        }
    }
}

// round 8
// speedup vs baseline: 1.8105x; 1.1693x over previous
#include <cuda_runtime.h>
#include <cuda_bf16.h>
#include <cstdint>

// Problem constants (match reference)
#define NN 100000      // nodes
#define DD 128         // feature dim
#define EE 200000      // edges per etype
#define ET 3           // etypes
#define NL 3           // layers
#define BN_EPS 1e-5f
#define PL (NN * DD)   // plane size (elements)

#define NTILE 782      // ceil(NN/128)
#define GRID_MM 148

#define SCAN_TOT (ET * NN)   // 300000
#define SCAN_BLK 1024
#define SCAN_NB  ((SCAN_TOT + SCAN_BLK - 1) / SCAN_BLK)   // 293

// ---------------- device scratch (no allocs allowed) ----------------
__device__ float g_h[(size_t)PL];                      // fp32 h between layers
__device__ float g_pre[(size_t)PL];                    // pre-BN layer output
__device__ int   g_cnt[SCAN_TOT];                      // degree, then CSR cursor
__device__ float g_inv[SCAN_TOT];
__device__ int   g_off[SCAN_TOT + 1];                  // CSR offsets
__device__ int   g_bsum[SCAN_NB];
__device__ int   g_csr[ET * EE];                       // src ids grouped by (e,dst)
__device__ float g_stats[2 * DD];
__device__ __nv_bfloat16 g_abf[(size_t)2 * PL];        // self A: [hi][lo] planes
__device__ __nv_bfloat16 g_nbf[(size_t)ET * 2 * PL];   // neigh A: per etype [hi][lo]
__device__ __nv_bfloat16 g_wbf[(size_t)NL * ET * 2 * 2 * DD * DD]; // [l][e][mat][prec][n][k]

// ---------------- helpers ----------------
__device__ __forceinline__ void split2(float a, float b, uint32_t& hi, uint32_t& lo) {
    asm("cvt.rn.bf16x2.f32 %0, %1, %2;" : "=r"(hi) : "f"(b), "f"(a));
    float ra = a - __uint_as_float(hi << 16);
    float rb = b - __uint_as_float(hi & 0xFFFF0000u);
    asm("cvt.rn.bf16x2.f32 %0, %1, %2;" : "=r"(lo) : "f"(rb), "f"(ra));
}
__device__ __forceinline__ uint32_t smem_u32(const void* p) {
    uint32_t a;
    asm("{ .reg .u64 t; cvta.to.shared.u64 t, %1; cvt.u32.u64 %0, t; }" : "=r"(a) : "l"(p));
    return a;
}
__device__ __forceinline__ void cpa16(uint32_t dst, const void* src, uint32_t srcsize) {
    asm volatile("cp.async.cg.shared.global [%0], [%1], 16, %2;"
                 :: "r"(dst), "l"(src), "r"(srcsize) : "memory");
}
#define CPA_COMMIT() asm volatile("cp.async.commit_group;" ::: "memory")
#define CPA_WAIT1()  asm volatile("cp.async.wait_group 1;" ::: "memory")

#define LDSM4(rg, addr) \
    asm volatile("ldmatrix.sync.aligned.m8n8.x4.shared.b16 {%0,%1,%2,%3}, [%4];" \
                 : "=r"((rg)[0]), "=r"((rg)[1]), "=r"((rg)[2]), "=r"((rg)[3]) : "r"(addr))
#define MMA16816(d, a, b0, b1) \
    asm volatile("mma.sync.aligned.m16n8k16.row.col.f32.bf16.bf16.f32 " \
                 "{%0,%1,%2,%3}, {%4,%5,%6,%7}, {%8,%9}, {%0,%1,%2,%3};" \
                 : "+f"((d)[0]), "+f"((d)[1]), "+f"((d)[2]), "+f"((d)[3]) \
                 : "r"((a)[0]), "r"((a)[1]), "r"((a)[2]), "r"((a)[3]), "r"(b0), "r"(b1))

// swizzled smem chunk offset: row stride 256B, 16B chunks XOR'd with row&7
#define CHOFF(row, chunk) ((uint32_t)((row) * 256 + ((((chunk) ^ ((row) & 7))) << 4)))

// ---------------- small kernels ----------------
__global__ void zero_f4(float4* __restrict__ p, int n4) {
    int i = blockIdx.x * blockDim.x + threadIdx.x;
    int stride = gridDim.x * blockDim.x;
    float4 z = make_float4(0.f, 0.f, 0.f, 0.f);
    for (; i < n4; i += stride) p[i] = z;
}

__global__ void count_deg(const int* __restrict__ dst, int* __restrict__ cnt, int total, int E) {
    int i = blockIdx.x * blockDim.x + threadIdx.x;
    if (i >= total) return;
    int e = i / E;
    atomicAdd(&cnt[e * NN + dst[i]], 1);
}

__global__ void make_inv(const int* __restrict__ cnt, float* __restrict__ inv, int total) {
    int i = blockIdx.x * blockDim.x + threadIdx.x;
    if (i >= total) return;
    inv[i] = 1.0f / fmaxf((float)cnt[i], 1.0f);
}

// ---- CSR build: 3-kernel exclusive scan + cursor fill ----
__global__ void scan1(const int* __restrict__ cnt, int* __restrict__ off, int* __restrict__ bsum) {
    __shared__ int sm[SCAN_BLK];
    int t = threadIdx.x, b = blockIdx.x;
    int i = b * SCAN_BLK + t;
    int v = (i < SCAN_TOT) ? cnt[i] : 0;
    sm[t] = v;
    __syncthreads();
    for (int d = 1; d < SCAN_BLK; d <<= 1) {
        int x = (t >= d) ? sm[t - d] : 0;
        __syncthreads();
        sm[t] += x;
        __syncthreads();
    }
    if (i < SCAN_TOT) off[i] = sm[t] - v;       // exclusive within block
    if (t == SCAN_BLK - 1) bsum[b] = sm[t];
}

__global__ void scan2(int* __restrict__ bsum) {
    __shared__ int sm[512];
    int t = threadIdx.x;
    int v = (t < SCAN_NB) ? bsum[t] : 0;
    sm[t] = v;
    __syncthreads();
    for (int d = 1; d < 512; d <<= 1) {
        int x = (t >= d) ? sm[t - d] : 0;
        __syncthreads();
        sm[t] += x;
        __syncthreads();
    }
    if (t < SCAN_NB) bsum[t] = sm[t] - v;        // exclusive block offsets
}

__global__ void scan3(int* __restrict__ off, const int* __restrict__ bsum) {
    int i = blockIdx.x * blockDim.x + threadIdx.x;
    if (i < SCAN_TOT) off[i] += bsum[i / SCAN_BLK];
    if (i == 0) off[SCAN_TOT] = ET * EE;
}

__global__ void fill_csr(const int* __restrict__ src, const int* __restrict__ dst,
                         const int* __restrict__ off, int* __restrict__ cursor,
                         int* __restrict__ csr, int total, int E) {
    int i = blockIdx.x * blockDim.x + threadIdx.x;
    if (i >= total) return;
    int e = i / E;
    int idx = e * NN + dst[i];
    int pos = off[idx] + atomicAdd(&cursor[idx], 1);
    csr[pos] = src[i];
}

// ---- gather-mean + bf16 split, one warp per (etype,node) ----
__global__ void gather_neigh(const float* __restrict__ h, const int* __restrict__ csr,
                             const int* __restrict__ off, const float* __restrict__ inv,
                             __nv_bfloat16* __restrict__ nbf) {
    int gw = (blockIdx.x * blockDim.x + threadIdx.x) >> 5;
    int lane = threadIdx.x & 31;
    if (gw >= ET * NN) return;
    int e = gw / NN;
    int node = gw - e * NN;
    int beg = off[gw], end = off[gw + 1];
    float a0 = 0.f, a1 = 0.f, a2 = 0.f, a3 = 0.f;
    int j = beg;
    // 2-wide unroll for MLP
    for (; j + 1 < end; j += 2) {
        int s0 = csr[j], s1 = csr[j + 1];
        float4 v0 = *(const float4*)(h + (size_t)s0 * DD + lane * 4);
        float4 v1 = *(const float4*)(h + (size_t)s1 * DD + lane * 4);
        a0 += v0.x + v1.x; a1 += v0.y + v1.y;
        a2 += v0.z + v1.z; a3 += v0.w + v1.w;
    }
    if (j < end) {
        int s = csr[j];
        float4 v = *(const float4*)(h + (size_t)s * DD + lane * 4);
        a0 += v.x; a1 += v.y; a2 += v.z; a3 += v.w;
    }
    float sc = inv[gw];
    a0 *= sc; a1 *= sc; a2 *= sc; a3 *= sc;
    uint32_t hi0, lo0, hi1, lo1;
    split2(a0, a1, hi0, lo0);
    split2(a2, a3, hi1, lo1);
    __nv_bfloat16* d = nbf + (size_t)e * 2 * PL;
    size_t p = (size_t)node * DD + lane * 4;
    *(uint2*)(d + p)      = make_uint2(hi0, hi1);
    *(uint2*)(d + PL + p) = make_uint2(lo0, lo1);
}

// weights -> transposed bf16 hi/lo, once per launch
__global__ void prep_weights(const float* __restrict__ Ws, const float* __restrict__ Wn,
                             __nv_bfloat16* __restrict__ out) {
    int i = blockIdx.x * blockDim.x + threadIdx.x;
    const int total = NL * ET * 2 * DD * DD;
    if (i >= total) return;
    int k  = i & 127;
    int n  = (i >> 7) & 127;
    int m  = (i >> 14) & 1;
    int le = i >> 15;
    const float* W = (m == 0 ? Ws : Wn) + (size_t)le * DD * DD;
    float x = W[k * DD + n];          // W[k][n] -> Bt[n][k]
    __nv_bfloat16 h = __float2bfloat16(x);
    float r = x - __bfloat162float(h);
    size_t base = (size_t)((le * 2 + m) * 2) * DD * DD;
    out[base + n * DD + k]           = h;
    out[base + DD * DD + n * DD + k] = __float2bfloat16(r);
}

// fp32 plane -> bf16 hi/lo planes (feat / layer-0 A)
__global__ void cvt_plain(const float* __restrict__ src, __nv_bfloat16* __restrict__ dst, int n8) {
    int i = blockIdx.x * blockDim.x + threadIdx.x;
    if (i >= n8) return;
    const float4* s = (const float4*)src + (size_t)i * 2;
    float4 v0 = s[0], v1 = s[1];
    uint32_t hi[4], lo[4];
    split2(v0.x, v0.y, hi[0], lo[0]); split2(v0.z, v0.w, hi[1], lo[1]);
    split2(v1.x, v1.y, hi[2], lo[2]); split2(v1.z, v1.w, hi[3], lo[3]);
    *(uint4*)(dst + (size_t)i * 8)      = make_uint4(hi[0], hi[1], hi[2], hi[3]);
    *(uint4*)(dst + PL + (size_t)i * 8) = make_uint4(lo[0], lo[1], lo[2], lo[3]);
}

// ---------------- BatchNorm ----------------
__global__ void bn_stats(const float* __restrict__ x, float* __restrict__ stats, int N) {
    int col = threadIdx.x;
    float s = 0.f, s2 = 0.f;
    for (int r = blockIdx.x; r < N; r += gridDim.x) {
        float v = x[(size_t)r * DD + col];
        s += v; s2 += v * v;
    }
    atomicAdd(&stats[col], s);
    atomicAdd(&stats[DD + col], s2);
}

// BN apply -> fp32 y AND bf16 hi/lo planes (inner layers)
__global__ void bn_apply_fused(const float* __restrict__ x, const float* __restrict__ stats,
                               const float* __restrict__ gamma, const float* __restrict__ beta,
                               float* __restrict__ y, __nv_bfloat16* __restrict__ abf, int N) {
    int c2 = threadIdx.x;               // 64 threads -> col pair
    int c0 = 2 * c2, c1 = c0 + 1;
    float invN = 1.0f / (float)N;
    float mu0 = stats[c0] * invN, mu1 = stats[c1] * invN;
    float va0 = stats[DD + c0] * invN - mu0 * mu0;
    float va1 = stats[DD + c1] * invN - mu1 * mu1;
    float sc0 = gamma[c0] * rsqrtf(va0 + BN_EPS);
    float sc1 = gamma[c1] * rsqrtf(va1 + BN_EPS);
    float sh0 = beta[c0] - mu0 * sc0;
    float sh1 = beta[c1] - mu1 * sc1;
    uint32_t* hip = (uint32_t*)abf;
    uint32_t* lop = (uint32_t*)(abf + PL);
    for (int r = blockIdx.x; r < N; r += gridDim.x) {
        size_t idx = (size_t)r * DD + c0;
        float2 v = *(const float2*)(x + idx);
        float y0 = v.x * sc0 + sh0;
        float y1 = v.y * sc1 + sh1;
        *(float2*)(y + idx) = make_float2(y0, y1);
        uint32_t hi, lo;
        split2(y0, y1, hi, lo);
        hip[idx >> 1] = hi;
        lop[idx >> 1] = lo;
    }
}

__global__ void bn_apply(const float* __restrict__ x, const float* __restrict__ stats,
                         const float* __restrict__ gamma, const float* __restrict__ beta,
                         float* __restrict__ y, int N) {
    int col = threadIdx.x;
    float invN = 1.0f / (float)N;
    float mu  = stats[col] * invN;
    float var = stats[DD + col] * invN - mu * mu;
    float sc  = gamma[col] * rsqrtf(var + BN_EPS);
    float sh  = beta[col] - mu * sc;
    for (int r = blockIdx.x; r < N; r += gridDim.x) {
        size_t idx = (size_t)r * DD + col;
        y[idx] = x[idx] * sc + sh;
    }
}

// ---------------- persistent cp.async-pipelined bf16 GEMM ----------------
#define SM_BIAS 0
#define SM_A0   2048
#define SM_B0   (2048 + 2 * 65536)
#define SMEM_TOTAL (2048 + 2 * 65536 + 3 * 32768)

extern __shared__ __align__(1024) char dsm[];

__device__ __forceinline__ void stageA(uint32_t dstbase, const __nv_bfloat16* __restrict__ g,
                                       int blockRow, int tid) {
#pragma unroll
    for (int p = 0; p < 8; ++p) {
        int c = tid + p * 512;
        int prec = c >> 11;
        int row  = (c >> 4) & 127;
        int ch   = c & 15;
        int rg = blockRow + row;
        int rs = rg < NN ? rg : 0;
        const void* src = g + (size_t)prec * PL + (size_t)rs * DD + ch * 8;
        cpa16(dstbase + prec * 32768 + CHOFF(row, ch), src, rg < NN ? 16u : 0u);
    }
}
__device__ __forceinline__ void stageB(uint32_t dstbase, const __nv_bfloat16* __restrict__ g,
                                       int tid) {
#pragma unroll
    for (int p = 0; p < 4; ++p) {
        int c = tid + p * 512;
        int row = c >> 4;
        int ch  = c & 15;
        cpa16(dstbase + CHOFF(row, ch), g + (size_t)row * DD + ch * 8, 16u);
    }
}

__device__ __forceinline__ void combo(uint32_t Abase, uint32_t Bbase,
                                      float acc[2][4][4], int lane, int wm, int wn) {
    int sub = lane >> 3, r = lane & 7;
    int arow0 = wm * 32 + r + (sub & 1) * 8;
    int aco = sub >> 1;
    int brow0 = wn * 32 + r + (sub >> 1) * 8;
    int bco = sub & 1;
#pragma unroll
    for (int k16 = 0; k16 < 8; ++k16) {
        uint32_t a[2][4];
#pragma unroll
        for (int mf = 0; mf < 2; ++mf) {
            int row = arow0 + mf * 16;
            LDSM4(a[mf], Abase + (uint32_t)(row * 256) + ((((k16 * 2 + aco) ^ (row & 7))) << 4));
        }
        uint32_t b[2][4];
#pragma unroll
        for (int n16 = 0; n16 < 2; ++n16) {
            int row = brow0 + n16 * 16;
            LDSM4(b[n16], Bbase + (uint32_t)(row * 256) + ((((k16 * 2 + bco) ^ (row & 7))) << 4));
        }
#pragma unroll
        for (int mf = 0; mf < 2; ++mf)
#pragma unroll
            for (int n16 = 0; n16 < 2; ++n16) {
                MMA16816(acc[mf][2 * n16],     a[mf], b[n16][0], b[n16][1]);
                MMA16816(acc[mf][2 * n16 + 1], a[mf], b[n16][2], b[n16][3]);
            }
    }
}

__global__ void __launch_bounds__(512, 1)
mm_layer(const __nv_bfloat16* __restrict__ abf, const __nv_bfloat16* __restrict__ nbf,
         const __nv_bfloat16* __restrict__ wbf_l, const float* __restrict__ bias_l,
         float* __restrict__ pre, int doRelu) {
    int tid = threadIdx.x;
    int lane = tid & 31;
    int w = tid >> 5;
    int wm = w & 3, wn = w >> 2;

    if (tid < ET * DD) ((float*)(dsm + SM_BIAS))[tid] = bias_l[tid];

    uint32_t sb = smem_u32(dsm);
    uint32_t Aaddr[2] = {sb + SM_A0, sb + SM_A0 + 65536};
    uint32_t Baddr[3] = {sb + SM_B0, sb + SM_B0 + 32768, sb + SM_B0 + 2 * 32768};

    const __nv_bfloat16* Asrc[6];
    const __nv_bfloat16* Bsrc[6];
#pragma unroll
    for (int p = 0; p < 6; ++p) {
        int e = p >> 1, mat = p & 1;
        Asrc[p] = mat ? (nbf + (size_t)e * 2 * PL) : abf;
        Bsrc[p] = wbf_l + (size_t)((e * 2 + mat) * 2) * DD * DD;
    }

    int tile0 = blockIdx.x;
    if (tile0 < NTILE) {
        stageA(Aaddr[0], Asrc[0], tile0 * 128, tid);
        stageB(Baddr[0], Bsrc[0], tid);
        CPA_COMMIT();
        stageB(Baddr[1], Bsrc[0] + DD * DD, tid);
        CPA_COMMIT();
    }

    for (int tile = tile0; tile < NTILE; tile += gridDim.x) {
        int blockRow = tile * 128;
        int nextRow = (tile + gridDim.x) * 128;
        bool hasNext = (tile + gridDim.x) < NTILE;

        float sum[2][4][4];
#pragma unroll
        for (int mf = 0; mf < 2; ++mf)
#pragma unroll
            for (int nb = 0; nb < 4; ++nb)
#pragma unroll
                for (int q = 0; q < 4; ++q) sum[mf][nb][q] = 0.f;

        float acc[2][4][4];

#pragma unroll 1
        for (int p = 0; p < 6; ++p) {
            __syncthreads();
            if (p < 5) {
                stageA(Aaddr[(p + 1) & 1], Asrc[p + 1], blockRow, tid);
                stageB(Baddr[(2 * p + 2) % 3], Bsrc[p + 1], tid);
            } else if (hasNext) {
                stageA(Aaddr[0], Asrc[0], nextRow, tid);
                stageB(Baddr[0], Bsrc[0], tid);
            }
            CPA_COMMIT();
            CPA_WAIT1();
            __syncthreads();

            uint32_t Acur = Aaddr[p & 1];
            uint32_t Hb = Baddr[(2 * p) % 3];
            uint32_t Lb = Baddr[(2 * p + 1) % 3];

            if (!(p & 1)) {
#pragma unroll
                for (int mf = 0; mf < 2; ++mf)
#pragma unroll
                    for (int nb = 0; nb < 4; ++nb)
#pragma unroll
                        for (int q = 0; q < 4; ++q) acc[mf][nb][q] = 0.f;
            }

            combo(Acur,         Hb, acc, lane, wm, wn);
            combo(Acur + 32768, Hb, acc, lane, wm, wn);
            __syncthreads();
            if (p < 5) {
                stageB(Baddr[(2 * p + 3) % 3], Bsrc[p + 1] + DD * DD, tid);
            } else if (hasNext) {
                stageB(Baddr[1], Bsrc[0] + DD * DD, tid);
            }
            CPA_COMMIT();
            combo(Acur, Lb, acc, lane, wm, wn);

            if (p & 1) {
                int e = p >> 1;
#pragma unroll
                for (int nb = 0; nb < 4; ++nb) {
                    float2 bb = *(const float2*)((const float*)(dsm + SM_BIAS) + e * DD +
                                                 wn * 32 + nb * 8 + (lane & 3) * 2);
#pragma unroll
                    for (int mf = 0; mf < 2; ++mf) {
                        float v0 = acc[mf][nb][0] + bb.x;
                        float v1 = acc[mf][nb][1] + bb.y;
                        float v2 = acc[mf][nb][2] + bb.x;
                        float v3 = acc[mf][nb][3] + bb.y;
                        if (doRelu) {
                            v0 = fmaxf(v0, 0.f); v1 = fmaxf(v1, 0.f);
                            v2 = fmaxf(v2, 0.f); v3 = fmaxf(v3, 0.f);
                        }
                        sum[mf][nb][0] += v0; sum[mf][nb][1] += v1;
                        sum[mf][nb][2] += v2; sum[mf][nb][3] += v3;
                    }
                }
            }
        }

#pragma unroll
        for (int mf = 0; mf < 2; ++mf) {
            int row0 = blockRow + wm * 32 + mf * 16 + (lane >> 2);
            int row1 = row0 + 8;
#pragma unroll
            for (int nb = 0; nb < 4; ++nb) {
                int col = wn * 32 + nb * 8 + (lane & 3) * 2;
                if (row0 < NN)
                    *(float2*)(pre + (size_t)row0 * DD + col) =
                        make_float2(sum[mf][nb][0], sum[mf][nb][1]);
                if (row1 < NN)
                    *(float2*)(pre + (size_t)row1 * DD + col) =
                        make_float2(sum[mf][nb][2], sum[mf][nb][3]);
            }
        }
    }
}

// ---------------- launch ----------------
extern "C" void kernel_launch(void* const* d_in, const int* in_sizes, int n_in,
                              void* d_out, int out_size) {
    const float* feat  = (const float*)d_in[0];
    const int*   src   = (const int*)d_in[1];
    const int*   dst   = (const int*)d_in[2];
    const float* Wself = (const float*)d_in[3];
    const float* Wngh  = (const float*)d_in[4];
    const float* bvec  = (const float*)d_in[5];
    const float* gamma = (const float*)d_in[6];
    const float* beta  = (const float*)d_in[7];

    float *h, *pre, *inv, *stats;
    int *cnt, *off, *bsum, *csr;
    __nv_bfloat16 *wbf, *abf, *nbf;
    cudaGetSymbolAddress((void**)&h,     g_h);
    cudaGetSymbolAddress((void**)&pre,   g_pre);
    cudaGetSymbolAddress((void**)&cnt,   g_cnt);
    cudaGetSymbolAddress((void**)&inv,   g_inv);
    cudaGetSymbolAddress((void**)&off,   g_off);
    cudaGetSymbolAddress((void**)&bsum,  g_bsum);
    cudaGetSymbolAddress((void**)&csr,   g_csr);
    cudaGetSymbolAddress((void**)&stats, g_stats);
    cudaGetSymbolAddress((void**)&wbf,   g_wbf);
    cudaGetSymbolAddress((void**)&abf,   g_abf);
    cudaGetSymbolAddress((void**)&nbf,   g_nbf);

    cudaFuncSetAttribute(mm_layer, cudaFuncAttributeMaxDynamicSharedMemorySize, SMEM_TOTAL);

    const int totE = ET * EE;

    // ---- CSR build (once per launch) ----
    zero_f4<<<1024, 256>>>((float4*)cnt, SCAN_TOT / 4);
    count_deg<<<(totE + 255) / 256, 256>>>(dst, cnt, totE, EE);
    make_inv<<<(SCAN_TOT + 255) / 256, 256>>>(cnt, inv, SCAN_TOT);
    scan1<<<SCAN_NB, SCAN_BLK>>>(cnt, off, bsum);
    scan2<<<1, 512>>>(bsum);
    scan3<<<(SCAN_TOT + 255) / 256, 256>>>(off, bsum);
    zero_f4<<<1024, 256>>>((float4*)cnt, SCAN_TOT / 4);
    fill_csr<<<(totE + 255) / 256, 256>>>(src, dst, off, cnt, csr, totE, EE);

    prep_weights<<<(NL * ET * 2 * DD * DD + 255) / 256, 256>>>(Wself, Wngh, wbf);
    cvt_plain<<<(PL / 8 + 255) / 256, 256>>>(feat, abf, PL / 8);

    const float* hin = feat;

    for (int l = 0; l < NL; ++l) {
        int doRelu = (l < NL - 1) ? 1 : 0;
        gather_neigh<<<(SCAN_TOT * 32 + 255) / 256, 256>>>(hin, csr, off, inv, nbf);
        mm_layer<<<GRID_MM, 512, SMEM_TOTAL>>>(abf, nbf,
                                               wbf + (size_t)l * ET * 2 * 2 * DD * DD,
                                               bvec + (size_t)l * ET * DD, pre, doRelu);
        zero_f4<<<1, 64>>>((float4*)stats, (2 * DD) / 4);
        bn_stats<<<512, DD>>>(pre, stats, NN);
        if (l < NL - 1) {
            bn_apply_fused<<<2048, 64>>>(pre, stats, gamma + (size_t)l * DD,
                                         beta + (size_t)l * DD, h, abf, NN);
            hin = h;
        } else {
            bn_apply<<<1024, DD>>>(pre, stats, gamma + (size_t)l * DD,
                                   beta + (size_t)l * DD, (float*)d_out, NN);
        }
    }
}

// round 9
// speedup vs baseline: 1.9643x; 1.0850x over previous
#include <cuda_runtime.h>
#include <cuda_bf16.h>
#include <cstdint>

// Problem constants (match reference)
#define NN 100000      // nodes
#define DD 128         // feature dim
#define EE 200000      // edges per etype
#define ET 3           // etypes
#define NL 3           // layers
#define BN_EPS 1e-5f
#define PL (NN * DD)   // plane size (elements)

#define NTILE 782      // ceil(NN/128)
#define GRID_MM 148

#define SCAN_TOT (ET * NN)   // 300000
#define SCAN_BLK 1024
#define SCAN_NB  ((SCAN_TOT + SCAN_BLK - 1) / SCAN_BLK)   // 293

// ---------------- device scratch (no allocs allowed) ----------------
__device__ float g_pre[(size_t)PL];                    // pre-BN layer output
__device__ int   g_cnt[SCAN_TOT];                      // degree, then CSR cursor
__device__ float g_inv[SCAN_TOT];
__device__ int   g_off[SCAN_TOT + 1];                  // CSR offsets
__device__ int   g_bsum[SCAN_NB];
__device__ int   g_csr[ET * EE];                       // src ids grouped by (e,dst)
__device__ float g_stats[NL * 2 * DD];                 // per-layer BN sum/sumsq
__device__ __nv_bfloat16 g_abf[(size_t)2 * PL];        // self A: [hi][lo] planes
__device__ __nv_bfloat16 g_nbf[(size_t)ET * 2 * PL];   // neigh A: per etype [hi][lo]
__device__ __nv_bfloat16 g_wbf[(size_t)NL * ET * 2 * 2 * DD * DD]; // [l][e][mat][prec][n][k]

// ---------------- helpers ----------------
__device__ __forceinline__ void split2(float a, float b, uint32_t& hi, uint32_t& lo) {
    asm("cvt.rn.bf16x2.f32 %0, %1, %2;" : "=r"(hi) : "f"(b), "f"(a));
    float ra = a - __uint_as_float(hi << 16);
    float rb = b - __uint_as_float(hi & 0xFFFF0000u);
    asm("cvt.rn.bf16x2.f32 %0, %1, %2;" : "=r"(lo) : "f"(rb), "f"(ra));
}
__device__ __forceinline__ uint32_t smem_u32(const void* p) {
    uint32_t a;
    asm("{ .reg .u64 t; cvta.to.shared.u64 t, %1; cvt.u32.u64 %0, t; }" : "=r"(a) : "l"(p));
    return a;
}
__device__ __forceinline__ void cpa16(uint32_t dst, const void* src, uint32_t srcsize) {
    asm volatile("cp.async.cg.shared.global [%0], [%1], 16, %2;"
                 :: "r"(dst), "l"(src), "r"(srcsize) : "memory");
}
#define CPA_COMMIT() asm volatile("cp.async.commit_group;" ::: "memory")
#define CPA_WAIT1()  asm volatile("cp.async.wait_group 1;" ::: "memory")

#define LDSM4(rg, addr) \
    asm volatile("ldmatrix.sync.aligned.m8n8.x4.shared.b16 {%0,%1,%2,%3}, [%4];" \
                 : "=r"((rg)[0]), "=r"((rg)[1]), "=r"((rg)[2]), "=r"((rg)[3]) : "r"(addr))
#define MMA16816(d, a, b0, b1) \
    asm volatile("mma.sync.aligned.m16n8k16.row.col.f32.bf16.bf16.f32 " \
                 "{%0,%1,%2,%3}, {%4,%5,%6,%7}, {%8,%9}, {%0,%1,%2,%3};" \
                 : "+f"((d)[0]), "+f"((d)[1]), "+f"((d)[2]), "+f"((d)[3]) \
                 : "r"((a)[0]), "r"((a)[1]), "r"((a)[2]), "r"((a)[3]), "r"(b0), "r"(b1))

// swizzled smem chunk offset: row stride 256B, 16B chunks XOR'd with row&7
#define CHOFF(row, chunk) ((uint32_t)((row) * 256 + ((((chunk) ^ ((row) & 7))) << 4)))

// ---------------- small kernels ----------------
__global__ void zero_f4(float4* __restrict__ p, int n4) {
    int i = blockIdx.x * blockDim.x + threadIdx.x;
    int stride = gridDim.x * blockDim.x;
    float4 z = make_float4(0.f, 0.f, 0.f, 0.f);
    for (; i < n4; i += stride) p[i] = z;
}

__global__ void count_deg(const int* __restrict__ dst, int* __restrict__ cnt, int total, int E) {
    int i = blockIdx.x * blockDim.x + threadIdx.x;
    if (i >= total) return;
    int e = i / E;
    atomicAdd(&cnt[e * NN + dst[i]], 1);
}

__global__ void make_inv(const int* __restrict__ cnt, float* __restrict__ inv, int total) {
    int i = blockIdx.x * blockDim.x + threadIdx.x;
    if (i >= total) return;
    inv[i] = 1.0f / fmaxf((float)cnt[i], 1.0f);
}

// ---- CSR build: 3-kernel exclusive scan + cursor fill ----
__global__ void scan1(const int* __restrict__ cnt, int* __restrict__ off, int* __restrict__ bsum) {
    __shared__ int sm[SCAN_BLK];
    int t = threadIdx.x, b = blockIdx.x;
    int i = b * SCAN_BLK + t;
    int v = (i < SCAN_TOT) ? cnt[i] : 0;
    sm[t] = v;
    __syncthreads();
    for (int d = 1; d < SCAN_BLK; d <<= 1) {
        int x = (t >= d) ? sm[t - d] : 0;
        __syncthreads();
        sm[t] += x;
        __syncthreads();
    }
    if (i < SCAN_TOT) off[i] = sm[t] - v;
    if (t == SCAN_BLK - 1) bsum[b] = sm[t];
}

__global__ void scan2(int* __restrict__ bsum) {
    __shared__ int sm[512];
    int t = threadIdx.x;
    int v = (t < SCAN_NB) ? bsum[t] : 0;
    sm[t] = v;
    __syncthreads();
    for (int d = 1; d < 512; d <<= 1) {
        int x = (t >= d) ? sm[t - d] : 0;
        __syncthreads();
        sm[t] += x;
        __syncthreads();
    }
    if (t < SCAN_NB) bsum[t] = sm[t] - v;
}

__global__ void scan3(int* __restrict__ off, const int* __restrict__ bsum) {
    int i = blockIdx.x * blockDim.x + threadIdx.x;
    if (i < SCAN_TOT) off[i] += bsum[i / SCAN_BLK];
    if (i == 0) off[SCAN_TOT] = ET * EE;
}

__global__ void fill_csr(const int* __restrict__ src, const int* __restrict__ dst,
                         const int* __restrict__ off, int* __restrict__ cursor,
                         int* __restrict__ csr, int total, int E) {
    int i = blockIdx.x * blockDim.x + threadIdx.x;
    if (i >= total) return;
    int e = i / E;
    int idx = e * NN + dst[i];
    int pos = off[idx] + atomicAdd(&cursor[idx], 1);
    csr[pos] = src[i];
}

// ---- gather-mean with inline BN affine + bf16 split, one warp per (etype,node) ----
// mean(BN(x)) = sc * mean(x) + sh * [deg>0]  (sc/sh per column)
__global__ void gather_neigh(const float* __restrict__ hsrc, const int* __restrict__ csr,
                             const int* __restrict__ off, const float* __restrict__ inv,
                             __nv_bfloat16* __restrict__ nbf,
                             const float* __restrict__ stats, const float* __restrict__ gamma,
                             const float* __restrict__ beta, int useBN) {
    int gw = (blockIdx.x * blockDim.x + threadIdx.x) >> 5;
    int lane = threadIdx.x & 31;
    if (gw >= ET * NN) return;
    int e = gw / NN;
    int node = gw - e * NN;

    float sc0 = 1.f, sc1 = 1.f, sc2 = 1.f, sc3 = 1.f;
    float sh0 = 0.f, sh1 = 0.f, sh2 = 0.f, sh3 = 0.f;
    if (useBN) {
        int c = lane * 4;
        const float invN = 1.0f / (float)NN;
        float4 s  = *(const float4*)(stats + c);
        float4 s2 = *(const float4*)(stats + DD + c);
        float4 g  = *(const float4*)(gamma + c);
        float4 bt = *(const float4*)(beta + c);
        float mu, var;
        mu = s.x * invN; var = s2.x * invN - mu * mu;
        sc0 = g.x * rsqrtf(var + BN_EPS); sh0 = bt.x - mu * sc0;
        mu = s.y * invN; var = s2.y * invN - mu * mu;
        sc1 = g.y * rsqrtf(var + BN_EPS); sh1 = bt.y - mu * sc1;
        mu = s.z * invN; var = s2.z * invN - mu * mu;
        sc2 = g.z * rsqrtf(var + BN_EPS); sh2 = bt.z - mu * sc2;
        mu = s.w * invN; var = s2.w * invN - mu * mu;
        sc3 = g.w * rsqrtf(var + BN_EPS); sh3 = bt.w - mu * sc3;
    }

    int beg = off[gw], end = off[gw + 1];
    float a0 = 0.f, a1 = 0.f, a2 = 0.f, a3 = 0.f;
    int j = beg;
    for (; j + 1 < end; j += 2) {
        int s0 = csr[j], s1 = csr[j + 1];
        float4 v0 = *(const float4*)(hsrc + (size_t)s0 * DD + lane * 4);
        float4 v1 = *(const float4*)(hsrc + (size_t)s1 * DD + lane * 4);
        a0 += v0.x + v1.x; a1 += v0.y + v1.y;
        a2 += v0.z + v1.z; a3 += v0.w + v1.w;
    }
    if (j < end) {
        int s = csr[j];
        float4 v = *(const float4*)(hsrc + (size_t)s * DD + lane * 4);
        a0 += v.x; a1 += v.y; a2 += v.z; a3 += v.w;
    }
    float m = inv[gw];
    float has = (end > beg) ? 1.0f : 0.0f;
    a0 = a0 * m * sc0 + sh0 * has;
    a1 = a1 * m * sc1 + sh1 * has;
    a2 = a2 * m * sc2 + sh2 * has;
    a3 = a3 * m * sc3 + sh3 * has;

    uint32_t hi0, lo0, hi1, lo1;
    split2(a0, a1, hi0, lo0);
    split2(a2, a3, hi1, lo1);
    __nv_bfloat16* d = nbf + (size_t)e * 2 * PL;
    size_t p = (size_t)node * DD + lane * 4;
    // streaming stores: nbf is written once, read once -> keep pre/abf in L2
    asm volatile("st.global.cs.v2.b32 [%0], {%1, %2};"
                 :: "l"((void*)(d + p)), "r"(hi0), "r"(hi1) : "memory");
    asm volatile("st.global.cs.v2.b32 [%0], {%1, %2};"
                 :: "l"((void*)(d + PL + p)), "r"(lo0), "r"(lo1) : "memory");
}

// weights -> transposed bf16 hi/lo, once per launch
__global__ void prep_weights(const float* __restrict__ Ws, const float* __restrict__ Wn,
                             __nv_bfloat16* __restrict__ out) {
    int i = blockIdx.x * blockDim.x + threadIdx.x;
    const int total = NL * ET * 2 * DD * DD;
    if (i >= total) return;
    int k  = i & 127;
    int n  = (i >> 7) & 127;
    int m  = (i >> 14) & 1;
    int le = i >> 15;
    const float* W = (m == 0 ? Ws : Wn) + (size_t)le * DD * DD;
    float x = W[k * DD + n];          // W[k][n] -> Bt[n][k]
    __nv_bfloat16 h = __float2bfloat16(x);
    float r = x - __bfloat162float(h);
    size_t base = (size_t)((le * 2 + m) * 2) * DD * DD;
    out[base + n * DD + k]           = h;
    out[base + DD * DD + n * DD + k] = __float2bfloat16(r);
}

// fp32 plane -> bf16 hi/lo planes (feat / layer-0 A)
__global__ void cvt_plain(const float* __restrict__ src, __nv_bfloat16* __restrict__ dst, int n8) {
    int i = blockIdx.x * blockDim.x + threadIdx.x;
    if (i >= n8) return;
    const float4* s = (const float4*)src + (size_t)i * 2;
    float4 v0 = s[0], v1 = s[1];
    uint32_t hi[4], lo[4];
    split2(v0.x, v0.y, hi[0], lo[0]); split2(v0.z, v0.w, hi[1], lo[1]);
    split2(v1.x, v1.y, hi[2], lo[2]); split2(v1.z, v1.w, hi[3], lo[3]);
    *(uint4*)(dst + (size_t)i * 8)      = make_uint4(hi[0], hi[1], hi[2], hi[3]);
    *(uint4*)(dst + PL + (size_t)i * 8) = make_uint4(lo[0], lo[1], lo[2], lo[3]);
}

// BN(pre) -> abf hi/lo planes (inner layers)
__global__ void abf_make(const float* __restrict__ pre, const float* __restrict__ stats,
                         const float* __restrict__ gamma, const float* __restrict__ beta,
                         __nv_bfloat16* __restrict__ abf) {
    __shared__ float sc[DD], sh[DD];
    int t = threadIdx.x;
    if (t < DD) {
        const float invN = 1.0f / (float)NN;
        float mu = stats[t] * invN;
        float var = stats[DD + t] * invN - mu * mu;
        float s = gamma[t] * rsqrtf(var + BN_EPS);
        sc[t] = s;
        sh[t] = beta[t] - mu * s;
    }
    __syncthreads();
    int i = blockIdx.x * blockDim.x + t;
    int stride = gridDim.x * blockDim.x;
    for (; i < PL / 8; i += stride) {
        const float4* s4 = (const float4*)pre + (size_t)i * 2;
        float4 v0 = s4[0], v1 = s4[1];
        int c = (i * 8) & 127;
        v0.x = v0.x * sc[c + 0] + sh[c + 0];
        v0.y = v0.y * sc[c + 1] + sh[c + 1];
        v0.z = v0.z * sc[c + 2] + sh[c + 2];
        v0.w = v0.w * sc[c + 3] + sh[c + 3];
        v1.x = v1.x * sc[c + 4] + sh[c + 4];
        v1.y = v1.y * sc[c + 5] + sh[c + 5];
        v1.z = v1.z * sc[c + 6] + sh[c + 6];
        v1.w = v1.w * sc[c + 7] + sh[c + 7];
        uint32_t hi[4], lo[4];
        split2(v0.x, v0.y, hi[0], lo[0]); split2(v0.z, v0.w, hi[1], lo[1]);
        split2(v1.x, v1.y, hi[2], lo[2]); split2(v1.z, v1.w, hi[3], lo[3]);
        *(uint4*)(abf + (size_t)i * 8)      = make_uint4(hi[0], hi[1], hi[2], hi[3]);
        *(uint4*)(abf + PL + (size_t)i * 8) = make_uint4(lo[0], lo[1], lo[2], lo[3]);
    }
}

// final BN apply -> d_out
__global__ void bn_apply(const float* __restrict__ x, const float* __restrict__ stats,
                         const float* __restrict__ gamma, const float* __restrict__ beta,
                         float* __restrict__ y, int N) {
    int col = threadIdx.x;
    float invN = 1.0f / (float)N;
    float mu  = stats[col] * invN;
    float var = stats[DD + col] * invN - mu * mu;
    float sc  = gamma[col] * rsqrtf(var + BN_EPS);
    float sh  = beta[col] - mu * sc;
    for (int r = blockIdx.x; r < N; r += gridDim.x) {
        size_t idx = (size_t)r * DD + col;
        y[idx] = x[idx] * sc + sh;
    }
}

// ---------------- persistent cp.async-pipelined bf16 GEMM + fused BN stats ----------------
#define SM_BIAS 0
#define SM_A0   2048
#define SM_B0   (2048 + 2 * 65536)
#define SMEM_TOTAL (2048 + 2 * 65536 + 3 * 32768)

extern __shared__ __align__(1024) char dsm[];

__device__ __forceinline__ void stageA(uint32_t dstbase, const __nv_bfloat16* __restrict__ g,
                                       int blockRow, int tid) {
#pragma unroll
    for (int p = 0; p < 8; ++p) {
        int c = tid + p * 512;
        int prec = c >> 11;
        int row  = (c >> 4) & 127;
        int ch   = c & 15;
        int rg = blockRow + row;
        int rs = rg < NN ? rg : 0;
        const void* src = g + (size_t)prec * PL + (size_t)rs * DD + ch * 8;
        cpa16(dstbase + prec * 32768 + CHOFF(row, ch), src, rg < NN ? 16u : 0u);
    }
}
__device__ __forceinline__ void stageB(uint32_t dstbase, const __nv_bfloat16* __restrict__ g,
                                       int tid) {
#pragma unroll
    for (int p = 0; p < 4; ++p) {
        int c = tid + p * 512;
        int row = c >> 4;
        int ch  = c & 15;
        cpa16(dstbase + CHOFF(row, ch), g + (size_t)row * DD + ch * 8, 16u);
    }
}

__device__ __forceinline__ void combo(uint32_t Abase, uint32_t Bbase,
                                      float acc[2][4][4], int lane, int wm, int wn) {
    int sub = lane >> 3, r = lane & 7;
    int arow0 = wm * 32 + r + (sub & 1) * 8;
    int aco = sub >> 1;
    int brow0 = wn * 32 + r + (sub >> 1) * 8;
    int bco = sub & 1;
#pragma unroll
    for (int k16 = 0; k16 < 8; ++k16) {
        uint32_t a[2][4];
#pragma unroll
        for (int mf = 0; mf < 2; ++mf) {
            int row = arow0 + mf * 16;
            LDSM4(a[mf], Abase + (uint32_t)(row * 256) + ((((k16 * 2 + aco) ^ (row & 7))) << 4));
        }
        uint32_t b[2][4];
#pragma unroll
        for (int n16 = 0; n16 < 2; ++n16) {
            int row = brow0 + n16 * 16;
            LDSM4(b[n16], Bbase + (uint32_t)(row * 256) + ((((k16 * 2 + bco) ^ (row & 7))) << 4));
        }
#pragma unroll
        for (int mf = 0; mf < 2; ++mf)
#pragma unroll
            for (int n16 = 0; n16 < 2; ++n16) {
                MMA16816(acc[mf][2 * n16],     a[mf], b[n16][0], b[n16][1]);
                MMA16816(acc[mf][2 * n16 + 1], a[mf], b[n16][2], b[n16][3]);
            }
    }
}

__global__ void __launch_bounds__(512, 1)
mm_layer(const __nv_bfloat16* __restrict__ abf, const __nv_bfloat16* __restrict__ nbf,
         const __nv_bfloat16* __restrict__ wbf_l, const float* __restrict__ bias_l,
         float* __restrict__ pre, float* __restrict__ stats, int doRelu) {
    int tid = threadIdx.x;
    int lane = tid & 31;
    int w = tid >> 5;
    int wm = w & 3, wn = w >> 2;

    if (tid < ET * DD) ((float*)(dsm + SM_BIAS))[tid] = bias_l[tid];

    uint32_t sb = smem_u32(dsm);
    uint32_t Aaddr[2] = {sb + SM_A0, sb + SM_A0 + 65536};
    uint32_t Baddr[3] = {sb + SM_B0, sb + SM_B0 + 32768, sb + SM_B0 + 2 * 32768};

    const __nv_bfloat16* Asrc[6];
    const __nv_bfloat16* Bsrc[6];
#pragma unroll
    for (int p = 0; p < 6; ++p) {
        int e = p >> 1, mat = p & 1;
        Asrc[p] = mat ? (nbf + (size_t)e * 2 * PL) : abf;
        Bsrc[p] = wbf_l + (size_t)((e * 2 + mat) * 2) * DD * DD;
    }

    int tile0 = blockIdx.x;
    if (tile0 < NTILE) {
        stageA(Aaddr[0], Asrc[0], tile0 * 128, tid);
        stageB(Baddr[0], Bsrc[0], tid);
        CPA_COMMIT();
        stageB(Baddr[1], Bsrc[0] + DD * DD, tid);
        CPA_COMMIT();
    }

    for (int tile = tile0; tile < NTILE; tile += gridDim.x) {
        int blockRow = tile * 128;
        int nextRow = (tile + gridDim.x) * 128;
        bool hasNext = (tile + gridDim.x) < NTILE;

        float sum[2][4][4];
#pragma unroll
        for (int mf = 0; mf < 2; ++mf)
#pragma unroll
            for (int nb = 0; nb < 4; ++nb)
#pragma unroll
                for (int q = 0; q < 4; ++q) sum[mf][nb][q] = 0.f;

        float acc[2][4][4];

#pragma unroll 1
        for (int p = 0; p < 6; ++p) {
            __syncthreads();
            if (p < 5) {
                stageA(Aaddr[(p + 1) & 1], Asrc[p + 1], blockRow, tid);
                stageB(Baddr[(2 * p + 2) % 3], Bsrc[p + 1], tid);
            } else if (hasNext) {
                stageA(Aaddr[0], Asrc[0], nextRow, tid);
                stageB(Baddr[0], Bsrc[0], tid);
            }
            CPA_COMMIT();
            CPA_WAIT1();
            __syncthreads();

            uint32_t Acur = Aaddr[p & 1];
            uint32_t Hb = Baddr[(2 * p) % 3];
            uint32_t Lb = Baddr[(2 * p + 1) % 3];

            if (!(p & 1)) {
#pragma unroll
                for (int mf = 0; mf < 2; ++mf)
#pragma unroll
                    for (int nb = 0; nb < 4; ++nb)
#pragma unroll
                        for (int q = 0; q < 4; ++q) acc[mf][nb][q] = 0.f;
            }

            combo(Acur,         Hb, acc, lane, wm, wn);
            combo(Acur + 32768, Hb, acc, lane, wm, wn);
            __syncthreads();
            if (p < 5) {
                stageB(Baddr[(2 * p + 3) % 3], Bsrc[p + 1] + DD * DD, tid);
            } else if (hasNext) {
                stageB(Baddr[1], Bsrc[0] + DD * DD, tid);
            }
            CPA_COMMIT();
            combo(Acur, Lb, acc, lane, wm, wn);

            if (p & 1) {
                int e = p >> 1;
#pragma unroll
                for (int nb = 0; nb < 4; ++nb) {
                    float2 bb = *(const float2*)((const float*)(dsm + SM_BIAS) + e * DD +
                                                 wn * 32 + nb * 8 + (lane & 3) * 2);
#pragma unroll
                    for (int mf = 0; mf < 2; ++mf) {
                        float v0 = acc[mf][nb][0] + bb.x;
                        float v1 = acc[mf][nb][1] + bb.y;
                        float v2 = acc[mf][nb][2] + bb.x;
                        float v3 = acc[mf][nb][3] + bb.y;
                        if (doRelu) {
                            v0 = fmaxf(v0, 0.f); v1 = fmaxf(v1, 0.f);
                            v2 = fmaxf(v2, 0.f); v3 = fmaxf(v3, 0.f);
                        }
                        sum[mf][nb][0] += v0; sum[mf][nb][1] += v1;
                        sum[mf][nb][2] += v2; sum[mf][nb][3] += v3;
                    }
                }
            }
        }

        // write sum -> pre, fused BN column stats
        float cs[4][2], cq[4][2];
#pragma unroll
        for (int nb = 0; nb < 4; ++nb) {
            cs[nb][0] = cs[nb][1] = 0.f;
            cq[nb][0] = cq[nb][1] = 0.f;
        }
#pragma unroll
        for (int mf = 0; mf < 2; ++mf) {
            int row0 = blockRow + wm * 32 + mf * 16 + (lane >> 2);
            int row1 = row0 + 8;
#pragma unroll
            for (int nb = 0; nb < 4; ++nb) {
                int col = wn * 32 + nb * 8 + (lane & 3) * 2;
                if (row0 < NN) {
                    float v0 = sum[mf][nb][0], v1 = sum[mf][nb][1];
                    *(float2*)(pre + (size_t)row0 * DD + col) = make_float2(v0, v1);
                    cs[nb][0] += v0; cq[nb][0] += v0 * v0;
                    cs[nb][1] += v1; cq[nb][1] += v1 * v1;
                }
                if (row1 < NN) {
                    float v2 = sum[mf][nb][2], v3 = sum[mf][nb][3];
                    *(float2*)(pre + (size_t)row1 * DD + col) = make_float2(v2, v3);
                    cs[nb][0] += v2; cq[nb][0] += v2 * v2;
                    cs[nb][1] += v3; cq[nb][1] += v3 * v3;
                }
            }
        }
        // reduce across lanes sharing (lane & 3)
#pragma unroll
        for (int m = 4; m <= 16; m <<= 1) {
#pragma unroll
            for (int nb = 0; nb < 4; ++nb) {
                cs[nb][0] += __shfl_xor_sync(0xffffffffu, cs[nb][0], m);
                cs[nb][1] += __shfl_xor_sync(0xffffffffu, cs[nb][1], m);
                cq[nb][0] += __shfl_xor_sync(0xffffffffu, cq[nb][0], m);
                cq[nb][1] += __shfl_xor_sync(0xffffffffu, cq[nb][1], m);
            }
        }
        if (lane < 4) {
#pragma unroll
            for (int nb = 0; nb < 4; ++nb) {
                int col = wn * 32 + nb * 8 + lane * 2;
                atomicAdd(&stats[col],          cs[nb][0]);
                atomicAdd(&stats[col + 1],      cs[nb][1]);
                atomicAdd(&stats[DD + col],     cq[nb][0]);
                atomicAdd(&stats[DD + col + 1], cq[nb][1]);
            }
        }
    }
}

// ---------------- launch ----------------
extern "C" void kernel_launch(void* const* d_in, const int* in_sizes, int n_in,
                              void* d_out, int out_size) {
    const float* feat  = (const float*)d_in[0];
    const int*   src   = (const int*)d_in[1];
    const int*   dst   = (const int*)d_in[2];
    const float* Wself = (const float*)d_in[3];
    const float* Wngh  = (const float*)d_in[4];
    const float* bvec  = (const float*)d_in[5];
    const float* gamma = (const float*)d_in[6];
    const float* beta  = (const float*)d_in[7];

    float *pre, *inv, *stats;
    int *cnt, *off, *bsum, *csr;
    __nv_bfloat16 *wbf, *abf, *nbf;
    cudaGetSymbolAddress((void**)&pre,   g_pre);
    cudaGetSymbolAddress((void**)&cnt,   g_cnt);
    cudaGetSymbolAddress((void**)&inv,   g_inv);
    cudaGetSymbolAddress((void**)&off,   g_off);
    cudaGetSymbolAddress((void**)&bsum,  g_bsum);
    cudaGetSymbolAddress((void**)&csr,   g_csr);
    cudaGetSymbolAddress((void**)&stats, g_stats);
    cudaGetSymbolAddress((void**)&wbf,   g_wbf);
    cudaGetSymbolAddress((void**)&abf,   g_abf);
    cudaGetSymbolAddress((void**)&nbf,   g_nbf);

    cudaFuncSetAttribute(mm_layer, cudaFuncAttributeMaxDynamicSharedMemorySize, SMEM_TOTAL);

    const int totE = ET * EE;

    // ---- CSR build + one-time prep (every launch; deterministic) ----
    zero_f4<<<1024, 256>>>((float4*)cnt, SCAN_TOT / 4);
    count_deg<<<(totE + 255) / 256, 256>>>(dst, cnt, totE, EE);
    make_inv<<<(SCAN_TOT + 255) / 256, 256>>>(cnt, inv, SCAN_TOT);
    scan1<<<SCAN_NB, SCAN_BLK>>>(cnt, off, bsum);
    scan2<<<1, 512>>>(bsum);
    scan3<<<(SCAN_TOT + 255) / 256, 256>>>(off, bsum);
    zero_f4<<<1024, 256>>>((float4*)cnt, SCAN_TOT / 4);
    fill_csr<<<(totE + 255) / 256, 256>>>(src, dst, off, cnt, csr, totE, EE);

    prep_weights<<<(NL * ET * 2 * DD * DD + 255) / 256, 256>>>(Wself, Wngh, wbf);
    cvt_plain<<<(PL / 8 + 255) / 256, 256>>>(feat, abf, PL / 8);
    zero_f4<<<1, 192>>>((float4*)stats, (NL * 2 * DD) / 4);

    for (int l = 0; l < NL; ++l) {
        int doRelu = (l < NL - 1) ? 1 : 0;
        float* st_l = stats + (size_t)l * 2 * DD;
        const float* st_prev = stats + (size_t)(l - 1) * 2 * DD;
        const float* hsrc = (l == 0) ? feat : pre;
        gather_neigh<<<(SCAN_TOT * 32 + 255) / 256, 256>>>(
            hsrc, csr, off, inv, nbf,
            (l == 0) ? (const float*)nullptr : st_prev,
            gamma + (size_t)(l - 1) * DD, beta + (size_t)(l - 1) * DD,
            (l == 0) ? 0 : 1);
        mm_layer<<<GRID_MM, 512, SMEM_TOTAL>>>(abf, nbf,
                                               wbf + (size_t)l * ET * 2 * 2 * DD * DD,
                                               bvec + (size_t)l * ET * DD, pre, st_l, doRelu);
        if (l < NL - 1) {
            abf_make<<<1184, 256>>>(pre, st_l, gamma + (size_t)l * DD,
                                    beta + (size_t)l * DD, abf);
        } else {
            bn_apply<<<1024, DD>>>(pre, st_l, gamma + (size_t)l * DD,
                                   beta + (size_t)l * DD, (float*)d_out, NN);
        }
    }
}